// round 6
// baseline (speedup 1.0000x reference)
#include <cuda_runtime.h>

// ---------------- problem constants ----------------
#define NBATCH 512
#define HID    512
#define DDIM   9
#define TENC   257            // encode steps (T+1)
#define TDEC   256            // decode steps
#define NSTEPS 513            // TENC + TDEC

// ---------------- tiling ----------------
#define MB 4                  // batch blocks
#define JB 32                 // hidden-unit blocks
#define NCTA (MB*JB)          // 128 CTAs, 1 per SM
#define NCTA_GRP JB           // CTAs per barrier group (share one batch block)
#define MT 128                // batch rows per CTA
#define JT 16                 // hidden units per CTA
#define CT 64                 // gate columns per CTA
#define NTHREADS 512
#define PF 8                  // prefetch depth in k

#define WS_STRIDE 68          // padded gate-weight row stride (bank-conflict-free)
#define XS_STRIDE 12

// smem layout in floats
#define WS_OFF   0
#define XS_OFF   (WS_OFF + HID*WS_STRIDE)     // 34816
#define WIH_OFF  (XS_OFF + MT*XS_STRIDE)      // +1536
#define BIAS_OFF (WIH_OFF + CT*XS_STRIDE)     // +768
#define SMEM_FLOATS (BIAS_OFF + CT)
#define SMEM_BYTES  (SMEM_FLOATS*4)           // ~148.7 KB

typedef unsigned long long ull;

// ---------------- device globals ----------------
// transposed + duplicated hidden state: hT[j*1024 + 2n] = hT[j*1024+2n+1] = h[n][j]
// padded for k-prefetch overread
__device__ __align__(16) float g_hT[2 * HID * 2 * NBATCH + 12 * 1024];
// row-major copy for the FC head
__device__ __align__(16) float g_hrm[2][NBATCH * HID];
__device__ unsigned g_cnt[4 * 32];   // per-mi-group counters, 128B apart
__device__ unsigned g_gen[4 * 32];

#define HT_BUF (HID * 2 * NBATCH)    // 1,048,576 floats per buffer

// ---------------- helpers ----------------
__device__ __forceinline__ float sigf(float x) { return 1.0f / (1.0f + __expf(-x)); }

__device__ __forceinline__ ull pack2(float lo, float hi) {
    ull r; asm("mov.b64 %0, {%1,%2};" : "=l"(r) : "f"(lo), "f"(hi)); return r;
}
__device__ __forceinline__ void unpack2(ull v, float& lo, float& hi) {
    asm("mov.b64 {%0,%1}, %2;" : "=f"(lo), "=f"(hi) : "l"(v));
}
// packed fma: acc(lo,hi) += (alo,ahi)*(blo,bhi); mov.b64 of aligned vector-load
// halves elides to register-pair renames in SASS.
__device__ __forceinline__ void ffma2f(ull& acc, float alo, float ahi,
                                       float blo, float bhi) {
    asm("{\n\t"
        ".reg .b64 ra, rb;\n\t"
        "mov.b64 ra, {%1,%2};\n\t"
        "mov.b64 rb, {%3,%4};\n\t"
        "fma.rn.f32x2 %0, ra, rb, %0;\n\t"
        "}"
        : "+l"(acc) : "f"(alo), "f"(ahi), "f"(blo), "f"(bhi));
}

// barrier over the 32 CTAs of one mi-group
__device__ __forceinline__ void group_sync(int mi) {
    __syncthreads();
    if (threadIdx.x == 0) {
        __threadfence();
        volatile unsigned* genp = &g_gen[mi * 32];
        unsigned target = *genp + 1u;
        if (atomicAdd(&g_cnt[mi * 32], 1u) == NCTA_GRP - 1u) {
            atomicExch(&g_cnt[mi * 32], 0u);
            __threadfence();
            atomicExch((unsigned*)&g_gen[mi * 32], target);
        } else {
            while ((int)(*genp - target) < 0) { }
        }
        __threadfence();
    }
    __syncthreads();
}

// FC head on row-major h: 36 outputs (4 rows x 9 dims) spread over 16 warps
__device__ __forceinline__ void fc_out(const float* __restrict__ h,
                                       const float* __restrict__ fcW,
                                       const float* __restrict__ fcb,
                                       float* __restrict__ out,
                                       int n0, int td, int wid, int lane) {
    for (int o = wid; o < 4 * DDIM; o += 16) {
        int rr = o / DDIM, d = o - rr * DDIM;
        int n = n0 + rr;
        const float* hr = h + (size_t)n * HID;
        const float* wr = fcW + d * HID;
        float s = 0.0f;
#pragma unroll
        for (int j = 0; j < 16; ++j)
            s += __ldcg(hr + j * 32 + lane) * wr[j * 32 + lane];
#pragma unroll
        for (int off = 16; off; off >>= 1)
            s += __shfl_xor_sync(0xffffffffu, s, off);
        if (lane == 0)
            out[((size_t)n * TDEC + td) * DDIM + d] = sigf(s + fcb[d]);
    }
}

// ---------------- persistent kernel ----------------
__global__ void __launch_bounds__(NTHREADS, 1)
lstm_kernel(const float* __restrict__ x, const float* __restrict__ W_ih,
            const float* __restrict__ W_hh, const float* __restrict__ b_ih,
            const float* __restrict__ b_hh, const float* __restrict__ fcW,
            const float* __restrict__ fcb, const float* __restrict__ h0,
            const float* __restrict__ c0, float* __restrict__ out) {
    extern __shared__ float sm[];
    float* ws   = sm + WS_OFF;    // [512][68] gate weights, logical col c=u*4+q
    float* xs   = sm + XS_OFF;    // [128][12] x tile
    float* wih  = sm + WIH_OFF;   // [64][12]
    float* bias = sm + BIAS_OFF;  // [64] = b_ih + b_hh

    const int tid  = threadIdx.x;
    const int bx   = blockIdx.x;
    const int mi   = bx >> 5, ji = bx & 31;
    const int m0   = mi * MT;
    const int j0   = ji * JT;
    const int lane = tid & 31;
    const int w    = tid >> 5;            // warp 0..15
    const int lr   = lane >> 3;           // 0..3 (row-pair within warp)
    const int lc   = lane & 7;            // 0..7 (unit pair)
    const int rowbase = (w << 3) + (lr << 1);   // 2 rows: rowbase, rowbase+1
    const int uj   = j0 + (lc << 1);      // 2 units: uj, uj+1

    // ---- one-time loads (weights resident in smem for the whole run) ----
    for (int idx = tid; idx < CT * HID; idx += NTHREADS) {
        int c = idx >> 9;
        int k = idx & 511;
        int g = (c & 3) * HID + j0 + (c >> 2);        // gate order i,f,g,o
        ws[k * WS_STRIDE + c + ((c >> 5) << 2)] = W_hh[(size_t)g * HID + k];
    }
    for (int idx = tid; idx < CT * DDIM; idx += NTHREADS) {
        int c = idx / DDIM, d = idx - c * DDIM;
        int g = (c & 3) * HID + j0 + (c >> 2);
        wih[c * XS_STRIDE + d] = W_ih[g * DDIM + d];
    }
    for (int c = tid; c < CT; c += NTHREADS) {
        int g = (c & 3) * HID + j0 + (c >> 2);
        bias[c] = b_ih[g] + b_hh[g];
    }
    // init h buffers (this CTA owns units j0..j0+15 x rows m0..m0+127)
    for (int idx = tid; idx < JT * MT; idx += NTHREADS) {
        int jj = j0 + (idx >> 7);
        int n  = m0 + (idx & 127);
        float v = h0[jj];
        g_hT[(size_t)jj * 1024 + 2 * n]     = v;
        g_hT[(size_t)jj * 1024 + 2 * n + 1] = v;
        g_hrm[0][(size_t)n * HID + jj] = v;
    }
    float c_reg[2][2];
    {
        float ca = c0[uj], cb = c0[uj + 1];
        c_reg[0][0] = ca; c_reg[1][0] = ca;
        c_reg[0][1] = cb; c_reg[1][1] = cb;
    }
    group_sync(mi);

    // A-operand base for this thread: hT[k*1024 + 2*(m0+rowbase)]
    const float* aT = g_hT + 2 * (m0 + rowbase);
    // weight base: physical col = lc*8 + pad
    const float* wp = ws + (lc << 3) + ((lc >> 2) << 2);

    // ---- time loop ----
    for (int s = 0; s < NSTEPS; ++s) {
        const int rb = s & 1;
        const float* __restrict__ aTin = aT + (size_t)rb * HT_BUF;
        const float* __restrict__ hrm_in = g_hrm[rb];
        float* __restrict__ hTout  = g_hT + (rb ^ 1) * (size_t)HT_BUF;
        float* __restrict__ hrmout = g_hrm[rb ^ 1];

        // prefetch first PF k's (L2 path; h changes every step)
        float4 pA[PF];
#pragma unroll
        for (int u = 0; u < PF; ++u)
            pA[u] = __ldcg((const float4*)(aTin + u * 1024));

        if (s >= TENC + 1)                 // emit previous decode step's output
            fc_out(hrm_in, fcW, fcb, out, m0 + (ji << 2), s - (TENC + 1), w, lane);

        const bool enc = (s < TENC);
        if (enc) {
            for (int idx = tid; idx < MT * DDIM; idx += NTHREADS) {
                int r = idx / DDIM, d = idx - r * DDIM;
                xs[r * XS_STRIDE + d] =
                    x[(size_t)(m0 + r) * (TENC * DDIM) + s * DDIM + d];
            }
            __syncthreads();
        }

        // accumulators: acc[row r][unit u][pair p], p=0:(i,f) p=1:(g,o)
        ull acc[2][2][2];
        {
            const float4 b1 = *(const float4*)(bias + (lc << 3));
            const float4 b2 = *(const float4*)(bias + (lc << 3) + 4);
#pragma unroll
            for (int r = 0; r < 2; ++r) {
                float sg[8] = {b1.x, b1.y, b1.z, b1.w, b2.x, b2.y, b2.z, b2.w};
                if (enc) {
                    const float* xrow = xs + (rowbase + r) * XS_STRIDE;
                    const float* wr   = wih + (lc << 3) * XS_STRIDE;
#pragma unroll
                    for (int d = 0; d < DDIM; ++d) {
                        float xv = xrow[d];
#pragma unroll
                        for (int q = 0; q < 8; ++q)
                            sg[q] += xv * wr[q * XS_STRIDE + d];
                    }
                }
                acc[r][0][0] = pack2(sg[0], sg[1]);
                acc[r][0][1] = pack2(sg[2], sg[3]);
                acc[r][1][0] = pack2(sg[4], sg[5]);
                acc[r][1][1] = pack2(sg[6], sg[7]);
            }
        }

        // main GEMM: no barriers, A streams from L2 with register prefetch
#pragma unroll 1
        for (int kb = 0; kb < HID; kb += PF) {
#pragma unroll
            for (int u = 0; u < PF; ++u) {
                const int kk = kb + u;
                const float4 A  = pA[u];   // (h_r0,h_r0,h_r1,h_r1)
                const float4 W1 = *(const float4*)(wp + kk * WS_STRIDE);     // unit0 i,f,g,o
                const float4 W2 = *(const float4*)(wp + kk * WS_STRIDE + 4); // unit1 i,f,g,o
                pA[u] = __ldcg((const float4*)(aTin + (kk + PF) * 1024));    // overreads pad
                ffma2f(acc[0][0][0], A.x, A.y, W1.x, W1.y);
                ffma2f(acc[0][0][1], A.x, A.y, W1.z, W1.w);
                ffma2f(acc[0][1][0], A.x, A.y, W2.x, W2.y);
                ffma2f(acc[0][1][1], A.x, A.y, W2.z, W2.w);
                ffma2f(acc[1][0][0], A.z, A.w, W1.x, W1.y);
                ffma2f(acc[1][0][1], A.z, A.w, W1.z, W1.w);
                ffma2f(acc[1][1][0], A.z, A.w, W2.x, W2.y);
                ffma2f(acc[1][1][1], A.z, A.w, W2.z, W2.w);
            }
        }

        // pointwise LSTM cell update
        float hv[2][2];
#pragma unroll
        for (int r = 0; r < 2; ++r)
#pragma unroll
            for (int u = 0; u < 2; ++u) {
                float iv, fv, gv, ov;
                unpack2(acc[r][u][0], iv, fv);
                unpack2(acc[r][u][1], gv, ov);
                float cn = sigf(fv) * c_reg[r][u] + sigf(iv) * tanhf(gv);
                c_reg[r][u] = cn;
                hv[r][u] = sigf(ov) * tanhf(cn);
            }
        // duplicated-transposed store: one STG.128 per unit
#pragma unroll
        for (int u = 0; u < 2; ++u) {
            float4 v = make_float4(hv[0][u], hv[0][u], hv[1][u], hv[1][u]);
            *(float4*)(hTout + (size_t)(uj + u) * 1024 + 2 * (m0 + rowbase)) = v;
        }
        // row-major store: one STG.64 per row
#pragma unroll
        for (int r = 0; r < 2; ++r) {
            float2 v = make_float2(hv[r][0], hv[r][1]);
            *(float2*)(hrmout + (size_t)(m0 + rowbase + r) * HID + uj) = v;
        }
        group_sync(mi);
    }

    // final decode step's output
    fc_out(g_hrm[NSTEPS & 1], fcW, fcb, out, m0 + (ji << 2), TDEC - 1, w, lane);
}

// ---------------- launch ----------------
extern "C" void kernel_launch(void* const* d_in, const int* in_sizes, int n_in,
                              void* d_out, int out_size) {
    (void)in_sizes; (void)n_in; (void)out_size;
    cudaFuncSetAttribute(lstm_kernel, cudaFuncAttributeMaxDynamicSharedMemorySize,
                         SMEM_BYTES);
    lstm_kernel<<<NCTA, NTHREADS, SMEM_BYTES>>>(
        (const float*)d_in[0],   // x
        (const float*)d_in[1],   // W_ih
        (const float*)d_in[2],   // W_hh
        (const float*)d_in[3],   // b_ih
        (const float*)d_in[4],   // b_hh
        (const float*)d_in[5],   // fc_W
        (const float*)d_in[6],   // fc_b
        (const float*)d_in[7],   // h0
        (const float*)d_in[8],   // c0
        (float*)d_out);
}

// round 7
// speedup vs baseline: 1.0021x; 1.0021x over previous
#include <cuda_runtime.h>

// ---------------- problem constants ----------------
#define NBATCH 512
#define HID    512
#define DDIM   9
#define TENC   257            // encode steps (T+1)
#define TDEC   256            // decode steps
#define NSTEPS 513            // TENC + TDEC

// ---------------- tiling ----------------
#define MB 4                  // batch blocks
#define JB 32                 // hidden-unit blocks
#define NCTA (MB*JB)          // 128 CTAs, 1 per SM
#define NCTA_GRP JB           // CTAs per barrier group (share one batch block)
#define MT 128                // batch rows per CTA
#define JT 16                 // hidden units per CTA
#define CT 64                 // gate columns per CTA
#define NTHREADS 512
#define PF 8                  // prefetch depth in k

#define WS_STRIDE 68          // padded gate-weight row stride (bank-conflict-free)
#define XS_STRIDE 12

// smem layout in floats
#define WS_OFF   0
#define XS_OFF   (WS_OFF + HID*WS_STRIDE)     // 34816
#define WIH_OFF  (XS_OFF + MT*XS_STRIDE)      // +1536
#define BIAS_OFF (WIH_OFF + CT*XS_STRIDE)     // +768
#define SMEM_FLOATS (BIAS_OFF + CT)
#define SMEM_BYTES  (SMEM_FLOATS*4)           // ~148.7 KB

typedef unsigned long long ull;

// ---------------- device globals ----------------
// transposed + duplicated hidden state: hT[j*1024 + 2n] = hT[j*1024+2n+1] = h[n][j]
// padded for k-prefetch overread
__device__ __align__(16) float g_hT[2 * HID * 2 * NBATCH + 12 * 1024];
// row-major copy for the FC head
__device__ __align__(16) float g_hrm[2][NBATCH * HID];
__device__ unsigned g_cnt[4 * 32];   // per-mi-group counters, 128B apart
__device__ unsigned g_gen[4 * 32];

#define HT_BUF (HID * 2 * NBATCH)    // 1,048,576 floats per buffer

// ---------------- helpers ----------------
__device__ __forceinline__ float sigf(float x) { return 1.0f / (1.0f + __expf(-x)); }

__device__ __forceinline__ ull pack2(float lo, float hi) {
    ull r; asm("mov.b64 %0, {%1,%2};" : "=l"(r) : "f"(lo), "f"(hi)); return r;
}
__device__ __forceinline__ void unpack2(ull v, float& lo, float& hi) {
    asm("mov.b64 {%0,%1}, %2;" : "=f"(lo), "=f"(hi) : "l"(v));
}
// packed fma: acc(lo,hi) += (alo,ahi)*(blo,bhi); mov.b64 of aligned vector-load
// halves elides to register-pair renames in SASS.
__device__ __forceinline__ void ffma2f(ull& acc, float alo, float ahi,
                                       float blo, float bhi) {
    asm("{\n\t"
        ".reg .b64 ra, rb;\n\t"
        "mov.b64 ra, {%1,%2};\n\t"
        "mov.b64 rb, {%3,%4};\n\t"
        "fma.rn.f32x2 %0, ra, rb, %0;\n\t"
        "}"
        : "+l"(acc) : "f"(alo), "f"(ahi), "f"(blo), "f"(bhi));
}

// barrier over the 32 CTAs of one mi-group
__device__ __forceinline__ void group_sync(int mi) {
    __syncthreads();
    if (threadIdx.x == 0) {
        __threadfence();
        volatile unsigned* genp = &g_gen[mi * 32];
        unsigned target = *genp + 1u;
        if (atomicAdd(&g_cnt[mi * 32], 1u) == NCTA_GRP - 1u) {
            atomicExch(&g_cnt[mi * 32], 0u);
            __threadfence();
            atomicExch((unsigned*)&g_gen[mi * 32], target);
        } else {
            while ((int)(*genp - target) < 0) { }
        }
        __threadfence();
    }
    __syncthreads();
}

// FC head on row-major h: 36 outputs (4 rows x 9 dims) spread over 16 warps
__device__ __forceinline__ void fc_out(const float* __restrict__ h,
                                       const float* __restrict__ fcW,
                                       const float* __restrict__ fcb,
                                       float* __restrict__ out,
                                       int n0, int td, int wid, int lane) {
    for (int o = wid; o < 4 * DDIM; o += 16) {
        int rr = o / DDIM, d = o - rr * DDIM;
        int n = n0 + rr;
        const float* hr = h + (size_t)n * HID;
        const float* wr = fcW + d * HID;
        float s = 0.0f;
#pragma unroll
        for (int j = 0; j < 16; ++j)
            s += __ldcg(hr + j * 32 + lane) * wr[j * 32 + lane];
#pragma unroll
        for (int off = 16; off; off >>= 1)
            s += __shfl_xor_sync(0xffffffffu, s, off);
        if (lane == 0)
            out[((size_t)n * TDEC + td) * DDIM + d] = sigf(s + fcb[d]);
    }
}

// ---------------- persistent kernel ----------------
__global__ void __launch_bounds__(NTHREADS, 1)
lstm_kernel(const float* __restrict__ x, const float* __restrict__ W_ih,
            const float* __restrict__ W_hh, const float* __restrict__ b_ih,
            const float* __restrict__ b_hh, const float* __restrict__ fcW,
            const float* __restrict__ fcb, const float* __restrict__ h0,
            const float* __restrict__ c0, float* __restrict__ out) {
    extern __shared__ float sm[];
    float* ws   = sm + WS_OFF;    // [512][68] gate weights, logical col c=u*4+q
    float* xs   = sm + XS_OFF;    // [128][12] x tile
    float* wih  = sm + WIH_OFF;   // [64][12]
    float* bias = sm + BIAS_OFF;  // [64] = b_ih + b_hh

    const int tid  = threadIdx.x;
    const int bx   = blockIdx.x;
    const int mi   = bx >> 5, ji = bx & 31;
    const int m0   = mi * MT;
    const int j0   = ji * JT;
    const int lane = tid & 31;
    const int w    = tid >> 5;            // warp 0..15
    const int lr   = lane >> 3;           // 0..3 (row-pair within warp)
    const int lc   = lane & 7;            // 0..7 (unit pair)
    const int rowbase = (w << 3) + (lr << 1);   // 2 rows: rowbase, rowbase+1
    const int uj   = j0 + (lc << 1);      // 2 units: uj, uj+1

    // ---- one-time loads (weights resident in smem for the whole run) ----
    for (int idx = tid; idx < CT * HID; idx += NTHREADS) {
        int c = idx >> 9;
        int k = idx & 511;
        int g = (c & 3) * HID + j0 + (c >> 2);        // gate order i,f,g,o
        ws[k * WS_STRIDE + c + ((c >> 5) << 2)] = W_hh[(size_t)g * HID + k];
    }
    for (int idx = tid; idx < CT * DDIM; idx += NTHREADS) {
        int c = idx / DDIM, d = idx - c * DDIM;
        int g = (c & 3) * HID + j0 + (c >> 2);
        wih[c * XS_STRIDE + d] = W_ih[g * DDIM + d];
    }
    for (int c = tid; c < CT; c += NTHREADS) {
        int g = (c & 3) * HID + j0 + (c >> 2);
        bias[c] = b_ih[g] + b_hh[g];
    }
    // init h buffers (this CTA owns units j0..j0+15 x rows m0..m0+127)
    for (int idx = tid; idx < JT * MT; idx += NTHREADS) {
        int jj = j0 + (idx >> 7);
        int n  = m0 + (idx & 127);
        float v = h0[jj];
        g_hT[(size_t)jj * 1024 + 2 * n]     = v;
        g_hT[(size_t)jj * 1024 + 2 * n + 1] = v;
        g_hrm[0][(size_t)n * HID + jj] = v;
    }
    float c_reg[2][2];
    {
        float ca = c0[uj], cb = c0[uj + 1];
        c_reg[0][0] = ca; c_reg[1][0] = ca;
        c_reg[0][1] = cb; c_reg[1][1] = cb;
    }
    group_sync(mi);

    // A-operand base for this thread: hT[k*1024 + 2*(m0+rowbase)]
    const float* aT = g_hT + 2 * (m0 + rowbase);
    // weight base: physical col = lc*8 + pad
    const float* wp = ws + (lc << 3) + ((lc >> 2) << 2);

    // ---- time loop ----
    for (int s = 0; s < NSTEPS; ++s) {
        const int rb = s & 1;
        const float* __restrict__ aTin = aT + (size_t)rb * HT_BUF;
        const float* __restrict__ hrm_in = g_hrm[rb];
        float* __restrict__ hTout  = g_hT + (rb ^ 1) * (size_t)HT_BUF;
        float* __restrict__ hrmout = g_hrm[rb ^ 1];

        // prefetch first PF k's (L2 path; h changes every step)
        float4 pA[PF];
#pragma unroll
        for (int u = 0; u < PF; ++u)
            pA[u] = __ldcg((const float4*)(aTin + u * 1024));

        if (s >= TENC + 1)                 // emit previous decode step's output
            fc_out(hrm_in, fcW, fcb, out, m0 + (ji << 2), s - (TENC + 1), w, lane);

        const bool enc = (s < TENC);
        if (enc) {
            for (int idx = tid; idx < MT * DDIM; idx += NTHREADS) {
                int r = idx / DDIM, d = idx - r * DDIM;
                xs[r * XS_STRIDE + d] =
                    x[(size_t)(m0 + r) * (TENC * DDIM) + s * DDIM + d];
            }
            __syncthreads();
        }

        // accumulators: acc[row r][unit u][pair p], p=0:(i,f) p=1:(g,o)
        ull acc[2][2][2];
        {
            const float4 b1 = *(const float4*)(bias + (lc << 3));
            const float4 b2 = *(const float4*)(bias + (lc << 3) + 4);
#pragma unroll
            for (int r = 0; r < 2; ++r) {
                float sg[8] = {b1.x, b1.y, b1.z, b1.w, b2.x, b2.y, b2.z, b2.w};
                if (enc) {
                    const float* xrow = xs + (rowbase + r) * XS_STRIDE;
                    const float* wr   = wih + (lc << 3) * XS_STRIDE;
#pragma unroll
                    for (int d = 0; d < DDIM; ++d) {
                        float xv = xrow[d];
#pragma unroll
                        for (int q = 0; q < 8; ++q)
                            sg[q] += xv * wr[q * XS_STRIDE + d];
                    }
                }
                acc[r][0][0] = pack2(sg[0], sg[1]);
                acc[r][0][1] = pack2(sg[2], sg[3]);
                acc[r][1][0] = pack2(sg[4], sg[5]);
                acc[r][1][1] = pack2(sg[6], sg[7]);
            }
        }

        // main GEMM: no barriers, A streams from L2 with register prefetch
#pragma unroll 1
        for (int kb = 0; kb < HID; kb += PF) {
#pragma unroll
            for (int u = 0; u < PF; ++u) {
                const int kk = kb + u;
                const float4 A  = pA[u];   // (h_r0,h_r0,h_r1,h_r1)
                const float4 W1 = *(const float4*)(wp + kk * WS_STRIDE);     // unit0 i,f,g,o
                const float4 W2 = *(const float4*)(wp + kk * WS_STRIDE + 4); // unit1 i,f,g,o
                pA[u] = __ldcg((const float4*)(aTin + (kk + PF) * 1024));    // overreads pad
                ffma2f(acc[0][0][0], A.x, A.y, W1.x, W1.y);
                ffma2f(acc[0][0][1], A.x, A.y, W1.z, W1.w);
                ffma2f(acc[0][1][0], A.x, A.y, W2.x, W2.y);
                ffma2f(acc[0][1][1], A.x, A.y, W2.z, W2.w);
                ffma2f(acc[1][0][0], A.z, A.w, W1.x, W1.y);
                ffma2f(acc[1][0][1], A.z, A.w, W1.z, W1.w);
                ffma2f(acc[1][1][0], A.z, A.w, W2.x, W2.y);
                ffma2f(acc[1][1][1], A.z, A.w, W2.z, W2.w);
            }
        }

        // pointwise LSTM cell update
        float hv[2][2];
#pragma unroll
        for (int r = 0; r < 2; ++r)
#pragma unroll
            for (int u = 0; u < 2; ++u) {
                float iv, fv, gv, ov;
                unpack2(acc[r][u][0], iv, fv);
                unpack2(acc[r][u][1], gv, ov);
                float cn = sigf(fv) * c_reg[r][u] + sigf(iv) * tanhf(gv);
                c_reg[r][u] = cn;
                hv[r][u] = sigf(ov) * tanhf(cn);
            }
        // duplicated-transposed store: one STG.128 per unit
#pragma unroll
        for (int u = 0; u < 2; ++u) {
            float4 v = make_float4(hv[0][u], hv[0][u], hv[1][u], hv[1][u]);
            *(float4*)(hTout + (size_t)(uj + u) * 1024 + 2 * (m0 + rowbase)) = v;
        }
        // row-major store: one STG.64 per row
#pragma unroll
        for (int r = 0; r < 2; ++r) {
            float2 v = make_float2(hv[r][0], hv[r][1]);
            *(float2*)(hrmout + (size_t)(m0 + rowbase + r) * HID + uj) = v;
        }
        group_sync(mi);
    }

    // final decode step's output
    fc_out(g_hrm[NSTEPS & 1], fcW, fcb, out, m0 + (ji << 2), TDEC - 1, w, lane);
}

// ---------------- launch ----------------
extern "C" void kernel_launch(void* const* d_in, const int* in_sizes, int n_in,
                              void* d_out, int out_size) {
    (void)in_sizes; (void)n_in; (void)out_size;
    cudaFuncSetAttribute(lstm_kernel, cudaFuncAttributeMaxDynamicSharedMemorySize,
                         SMEM_BYTES);
    lstm_kernel<<<NCTA, NTHREADS, SMEM_BYTES>>>(
        (const float*)d_in[0],   // x
        (const float*)d_in[1],   // W_ih
        (const float*)d_in[2],   // W_hh
        (const float*)d_in[3],   // b_ih
        (const float*)d_in[4],   // b_hh
        (const float*)d_in[5],   // fc_W
        (const float*)d_in[6],   // fc_b
        (const float*)d_in[7],   // h0
        (const float*)d_in[8],   // c0
        (float*)d_out);
}

// round 9
// speedup vs baseline: 1.3254x; 1.3226x over previous
#include <cuda_runtime.h>
#include <cstdint>

#define NBATCH 512
#define HID 512
#define DDIM 9
#define TENC 257
#define TDEC 256
#define NSTEPS 513
#define KC 32
#define NCHUNK 16
#define NCTA 128
#define NTHREADS 256
#define XPS 68

// smem layout (bytes)
#define SM_BIAS 0
#define SM_WIH 256
#define SM_XP 3584
#define SM_DS (SM_XP + 128*XPS*4)          // 38400
#define SM_B0 73728
#define AHSZ 16384
#define WHSZ 8192
#define BUFSZ (2*AHSZ + 2*WHSZ)            // 49152
#define SM_AHI(b) (SM_B0 + (b)*BUFSZ)
#define SM_ALO(b) (SM_AHI(b) + AHSZ)
#define SM_WHI(b) (SM_ALO(b) + AHSZ)
#define SM_WLO(b) (SM_WHI(b) + WHSZ)
#define SMEM_BYTES (SM_B0 + 2*BUFSZ)       // 172032

__device__ __align__(16) float g_whi[4*HID*HID];   // W_hh hi, rows c = u*4+q (i,f,g,o interleaved)
__device__ __align__(16) float g_wlo[4*HID*HID];   // residual
__device__ __align__(16) float g_h[2][NBATCH*HID];
__device__ unsigned s_cnt[5*32];
__device__ unsigned s_gen[5*32];

__device__ __forceinline__ float sigf(float x){ return 1.0f/(1.0f+__expf(-x)); }
__device__ __forceinline__ float tf32hi(float v){
    uint32_t u; asm("cvt.rna.tf32.f32 %0, %1;" : "=r"(u) : "f"(v)); return __uint_as_float(u);
}
__device__ __forceinline__ void mma8(float* d, const float4& a, const float2& b){
    asm volatile("mma.sync.aligned.m16n8k8.row.col.f32.tf32.tf32.f32 "
        "{%0,%1,%2,%3}, {%4,%5,%6,%7}, {%8,%9}, {%0,%1,%2,%3};"
        : "+f"(d[0]), "+f"(d[1]), "+f"(d[2]), "+f"(d[3])
        : "r"(__float_as_uint(a.x)), "r"(__float_as_uint(a.y)),
          "r"(__float_as_uint(a.z)), "r"(__float_as_uint(a.w)),
          "r"(__float_as_uint(b.x)), "r"(__float_as_uint(b.y)));
}

__device__ __forceinline__ void bar_sync(int g, unsigned count){
    __syncthreads();
    if (threadIdx.x == 0) {
        __threadfence();
        volatile unsigned* genp = &s_gen[g*32];
        unsigned target = *genp + 1u;
        if (atomicAdd(&s_cnt[g*32], 1u) == count - 1u) {
            atomicExch(&s_cnt[g*32], 0u);
            __threadfence();
            atomicExch((unsigned*)&s_gen[g*32], target);
        } else {
            while ((int)(*genp - target) < 0) { }
        }
        __threadfence();
    }
    __syncthreads();
}

__device__ __forceinline__ void fc_out(const float* __restrict__ h,
                                       const float* __restrict__ fcW,
                                       const float* __restrict__ fcb,
                                       float* __restrict__ out,
                                       int n0, int td, int wid, int lane){
    for (int o = wid; o < 4*DDIM; o += 8) {
        int rr = o / DDIM, d = o - rr*DDIM;
        int n = n0 + rr;
        const float* hr = h + (size_t)n*HID;
        const float* wr = fcW + d*HID;
        float s = 0.0f;
#pragma unroll
        for (int j = 0; j < 16; ++j)
            s += __ldcg(hr + j*32 + lane) * wr[j*32 + lane];
#pragma unroll
        for (int off = 16; off; off >>= 1)
            s += __shfl_xor_sync(0xffffffffu, s, off);
        if (lane == 0)
            out[((size_t)n*TDEC + td)*DDIM + d] = sigf(s + fcb[d]);
    }
}

__global__ void __launch_bounds__(NTHREADS, 1)
lstm_kernel(const float* __restrict__ x, const float* __restrict__ W_ih,
            const float* __restrict__ W_hh, const float* __restrict__ b_ih,
            const float* __restrict__ b_hh, const float* __restrict__ fcW,
            const float* __restrict__ fcb, const float* __restrict__ h0,
            const float* __restrict__ c0, float* __restrict__ out){
    extern __shared__ char smem[];
    float* bias = (float*)(smem + SM_BIAS);
    float* wih  = (float*)(smem + SM_WIH);
    float* xp   = (float*)(smem + SM_XP);
    float* ds   = (float*)(smem + SM_DS);

    const int tid = threadIdx.x, bx = blockIdx.x;
    const int mb = bx >> 5, gb = bx & 31;
    const int m0 = mb * 128;
    const int lane = tid & 31, wid = tid >> 5;
    const int wm = wid & 1, wn = wid >> 1;     // warp tile: rows 64*wm, cols 16*wn

    // ---- one-time init ----
    // W_hh split + rearrange: g_whi row cg = u*4+q  <-  W_hh row q*512+u
    for (int idx = bx*8192 + tid; idx < (bx+1)*8192; idx += NTHREADS) {
        int cg = idx >> 9, k = idx & 511;
        int u = cg >> 2, q = cg & 3;
        float wv = W_hh[((size_t)(q*HID + u))*HID + k];
        float hi = tf32hi(wv);
        g_whi[idx] = hi; g_wlo[idx] = wv - hi;
    }
    for (int c = tid; c < 64; c += NTHREADS) {
        int gr = (c & 3)*HID + gb*16 + (c >> 2);
        bias[c] = b_ih[gr] + b_hh[gr];
        for (int d = 0; d < DDIM; ++d) wih[c*12 + d] = W_ih[gr*DDIM + d];
    }
    for (int idx = bx*2048 + tid; idx < (bx+1)*2048; idx += NTHREADS) {
        int r = idx >> 9, j = idx & 511;
        g_h[0][(size_t)r*HID + j] = h0[j];
    }
    float c_reg[16];
    if (tid < 128)
#pragma unroll
        for (int u = 0; u < 16; ++u) c_reg[u] = c0[gb*16 + u];
    bar_sync(4, NCTA);

    const float* whig = g_whi + (size_t)(gb*64)*HID;
    const float* wlog = g_wlo + (size_t)(gb*64)*HID;

    // staging indices
    const int arow = tid >> 1, ahalf = tid & 1;          // A: row, k-half
    const int wc = tid & 63, wk = tid >> 6;              // W: gate col, k-segment(8)
    int aoff[4];
#pragma unroll
    for (int j = 0; j < 4; ++j) {
        int kq = ahalf*4 + j;
        aoff[j] = ((kq>>1)*8 + (arow>>4))*512
                + (((arow>>3)&1) + 2*(kq&1))*128 + (arow&7)*16;
    }
    const int woff = (wk*8 + (wc>>3))*256 + (wc&7)*16;
    const float* asrc0 = (const float*)0;

    // ---- time loop ----
    for (int s = 0; s < NSTEPS; ++s) {
        const int rb = s & 1;
        const float* __restrict__ hin = g_h[rb];
        float* __restrict__ hout = g_h[rb ^ 1];
        const bool enc = (s < TENC);

        float d[4][2][4];
#pragma unroll
        for (int mt = 0; mt < 4; ++mt)
#pragma unroll
            for (int nt = 0; nt < 2; ++nt)
#pragma unroll
                for (int q = 0; q < 4; ++q) d[mt][nt][q] = 0.0f;

        // prefetch chunk 0
        float4 vA[4], vWh[2], vWl[2];
        {
            const float* src = hin + (size_t)(m0 + arow)*HID + ahalf*16;
#pragma unroll
            for (int j = 0; j < 4; ++j) vA[j] = __ldcg((const float4*)(src + j*4));
            const float* sh = whig + (size_t)wc*HID + wk*8;
            const float* sl = wlog + (size_t)wc*HID + wk*8;
            vWh[0] = __ldcg((const float4*)sh);  vWh[1] = __ldcg((const float4*)(sh+4));
            vWl[0] = __ldcg((const float4*)sl);  vWl[1] = __ldcg((const float4*)(sl+4));
        }

        if (s >= TENC + 1)
            fc_out(hin, fcW, fcb, out, m0 + gb*4, s - (TENC+1), wid, lane);

        if (enc) {   // x-projection + bias -> xp[row][64]; thread: row=tid>>1, 32-col half
            const int xrow = tid >> 1, cb = (tid & 1)*32;
            float xv[DDIM];
#pragma unroll
            for (int dd = 0; dd < DDIM; ++dd)
                xv[dd] = __ldg(x + (size_t)(m0 + xrow)*(TENC*DDIM) + s*DDIM + dd);
            float sg[32];
#pragma unroll
            for (int c = 0; c < 32; ++c) sg[c] = bias[cb + c];
#pragma unroll
            for (int dd = 0; dd < DDIM; ++dd)
#pragma unroll
                for (int c = 0; c < 32; ++c) sg[c] += xv[dd]*wih[(cb + c)*12 + dd];
#pragma unroll
            for (int c = 0; c < 32; c += 4)
                *(float4*)(xp + xrow*XPS + cb + c) =
                    make_float4(sg[c], sg[c+1], sg[c+2], sg[c+3]);
        }

        // ---- chunk loop ----
        for (int ch = 0; ch < NCHUNK; ++ch) {
            const int b = ch & 1;
            // stage prefetched regs -> smem (split A hi/lo at store time)
#pragma unroll
            for (int j = 0; j < 4; ++j) {
                float4 v = vA[j];
                float4 hi = make_float4(tf32hi(v.x), tf32hi(v.y), tf32hi(v.z), tf32hi(v.w));
                float4 lo = make_float4(v.x-hi.x, v.y-hi.y, v.z-hi.z, v.w-hi.w);
                *(float4*)(smem + SM_AHI(b) + aoff[j]) = hi;
                *(float4*)(smem + SM_ALO(b) + aoff[j]) = lo;
            }
            *(float4*)(smem + SM_WHI(b) + woff)       = vWh[0];
            *(float4*)(smem + SM_WHI(b) + woff + 128) = vWh[1];
            *(float4*)(smem + SM_WLO(b) + woff)       = vWl[0];
            *(float4*)(smem + SM_WLO(b) + woff + 128) = vWl[1];
            __syncthreads();

            if (ch < NCHUNK-1) {   // prefetch next chunk (latency hidden by compute)
                const int kc = (ch+1)*KC;
                const float* src = hin + (size_t)(m0 + arow)*HID + kc + ahalf*16;
#pragma unroll
                for (int j = 0; j < 4; ++j) vA[j] = __ldcg((const float4*)(src + j*4));
                const float* sh = whig + (size_t)wc*HID + kc + wk*8;
                const float* sl = wlog + (size_t)wc*HID + kc + wk*8;
                vWh[0] = __ldcg((const float4*)sh);  vWh[1] = __ldcg((const float4*)(sh+4));
                vWl[0] = __ldcg((const float4*)sl);  vWl[1] = __ldcg((const float4*)(sl+4));
            }

            // compute: 4 k8-steps x (4 m-tiles x 2 n-tiles x 3 passes)
            const float* ah = (const float*)(smem + SM_AHI(b));
            const float* al = (const float*)(smem + SM_ALO(b));
            const float* bh = (const float*)(smem + SM_WHI(b));
            const float* bl = (const float*)(smem + SM_WLO(b));
#pragma unroll
            for (int kb = 0; kb < 4; ++kb) {
                const int abase = (kb*8 + wm*4)*128 + lane;
                const int bbase = (kb*8 + wn*2)*64 + lane;
                float4 Ah[4], Al[4];
#pragma unroll
                for (int mt = 0; mt < 4; ++mt) {
                    const int o = abase + mt*128;
                    Ah[mt] = make_float4(ah[o], ah[o+32], ah[o+64], ah[o+96]);
                    Al[mt] = make_float4(al[o], al[o+32], al[o+64], al[o+96]);
                }
                float2 Bh[2], Bl[2];
#pragma unroll
                for (int nt = 0; nt < 2; ++nt) {
                    const int o = bbase + nt*64;
                    Bh[nt] = make_float2(bh[o], bh[o+32]);
                    Bl[nt] = make_float2(bl[o], bl[o+32]);
                }
#pragma unroll
                for (int mt = 0; mt < 4; ++mt)
#pragma unroll
                    for (int nt = 0; nt < 2; ++nt) {
                        mma8(d[mt][nt], Ah[mt], Bh[nt]);
                        mma8(d[mt][nt], Ah[mt], Bl[nt]);
                        mma8(d[mt][nt], Al[mt], Bh[nt]);
                    }
            }
        }

        // ---- epilogue: dump D -> smem, row-threads do the cell update ----
        {
            const int g = lane >> 2, tq = lane & 3;
#pragma unroll
            for (int mt = 0; mt < 4; ++mt)
#pragma unroll
                for (int nt = 0; nt < 2; ++nt) {
                    const int row = wm*64 + mt*16 + g;
                    const int col = wn*16 + nt*8 + tq*2;
                    *(float2*)(ds + row*XPS + col)     = make_float2(d[mt][nt][0], d[mt][nt][1]);
                    *(float2*)(ds + (row+8)*XPS + col) = make_float2(d[mt][nt][2], d[mt][nt][3]);
                }
        }
        __syncthreads();
        if (tid < 128) {
            const int row = tid;
            float hv[16];
#pragma unroll
            for (int u = 0; u < 16; ++u) {
                float4 gv = *(float4*)(ds + row*XPS + u*4);
                float ai, af, ag, ao;
                if (enc) {
                    float4 a = *(float4*)(xp + row*XPS + u*4);
                    ai = a.x; af = a.y; ag = a.z; ao = a.w;
                } else {
                    ai = bias[u*4]; af = bias[u*4+1]; ag = bias[u*4+2]; ao = bias[u*4+3];
                }
                float iv = gv.x + ai, fv = gv.y + af, gg = gv.z + ag, ov = gv.w + ao;
                float cn = sigf(fv)*c_reg[u] + sigf(iv)*tanhf(gg);
                c_reg[u] = cn;
                hv[u] = sigf(ov)*tanhf(cn);
            }
            float* hw = hout + (size_t)(m0 + row)*HID + gb*16;
#pragma unroll
            for (int u = 0; u < 16; u += 4)
                *(float4*)(hw + u) = make_float4(hv[u], hv[u+1], hv[u+2], hv[u+3]);
        }
        bar_sync(mb, 32);
    }

    fc_out(g_h[NSTEPS & 1], fcW, fcb, out, m0 + gb*4, TDEC - 1, wid, lane);
}

extern "C" void kernel_launch(void* const* d_in, const int* in_sizes, int n_in,
                              void* d_out, int out_size){
    (void)in_sizes; (void)n_in; (void)out_size;
    cudaFuncSetAttribute(lstm_kernel, cudaFuncAttributeMaxDynamicSharedMemorySize,
                         SMEM_BYTES);
    lstm_kernel<<<NCTA, NTHREADS, SMEM_BYTES>>>(
        (const float*)d_in[0], (const float*)d_in[1], (const float*)d_in[2],
        (const float*)d_in[3], (const float*)d_in[4], (const float*)d_in[5],
        (const float*)d_in[6], (const float*)d_in[7], (const float*)d_in[8],
        (float*)d_out);
}

// round 10
// speedup vs baseline: 1.8198x; 1.3730x over previous
#include <cuda_runtime.h>
#include <cstdint>

#define NBATCH 512
#define HID 512
#define DDIM 9
#define TENC 257
#define TDEC 256
#define NSTEPS 513
#define NCHUNK 16
#define NCTA 128
#define NTHREADS 512
#define XPS 68

// smem layout (bytes)
#define SM_BIAS 0
#define SM_WIH  256
#define SM_XP   3584
#define SM_DS   (SM_XP + 128*XPS*4)     // 38400
#define SM_HF   (SM_DS + 128*XPS*4)     // 73216  (8KB fragment-order h staging)
#define SM_B0   81920
#define AHSZ 16384
#define WHSZ 8192
#define BUFSZ (2*AHSZ + 2*WHSZ)         // 49152
#define SM_AHI(b) (SM_B0 + (b)*BUFSZ)
#define SM_ALO(b) (SM_AHI(b) + AHSZ)
#define SM_WHI(b) (SM_ALO(b) + AHSZ)
#define SM_WLO(b) (SM_WHI(b) + WHSZ)
#define SMEM_BYTES (SM_B0 + 2*BUFSZ)    // 180224

#define HFBUF (4*65536)                 // fragment-ordered h floats per time-buffer

__device__ __align__(16) float g_whi[32*32768];      // per-gb fragment-ordered W hi
__device__ __align__(16) float g_wlo[32*32768];      // residual
__device__ __align__(16) float g_hf[2][HFBUF];       // fragment-ordered h (fp32)
__device__ __align__(16) float g_hrm[2][NBATCH*HID]; // row-major h for FC head
__device__ unsigned s_cnt[5*32];
__device__ unsigned s_gen[5*32];

__device__ __forceinline__ float sigf(float x){ return 1.0f/(1.0f+__expf(-x)); }
__device__ __forceinline__ float tf32hi(float v){
    uint32_t u; asm("cvt.rna.tf32.f32 %0, %1;" : "=r"(u) : "f"(v)); return __uint_as_float(u);
}
__device__ __forceinline__ void mma8(float* d, const float4& a, const float2& b){
    asm volatile("mma.sync.aligned.m16n8k8.row.col.f32.tf32.tf32.f32 "
        "{%0,%1,%2,%3}, {%4,%5,%6,%7}, {%8,%9}, {%0,%1,%2,%3};"
        : "+f"(d[0]), "+f"(d[1]), "+f"(d[2]), "+f"(d[3])
        : "r"(__float_as_uint(a.x)), "r"(__float_as_uint(a.y)),
          "r"(__float_as_uint(a.z)), "r"(__float_as_uint(a.w)),
          "r"(__float_as_uint(b.x)), "r"(__float_as_uint(b.y)));
}

__device__ __forceinline__ void bar_sync(int g, unsigned count){
    __syncthreads();
    if (threadIdx.x == 0) {
        __threadfence();
        volatile unsigned* genp = &s_gen[g*32];
        unsigned target = *genp + 1u;
        if (atomicAdd(&s_cnt[g*32], 1u) == count - 1u) {
            atomicExch(&s_cnt[g*32], 0u);
            __threadfence();
            atomicExch((unsigned*)&s_gen[g*32], target);
        } else {
            while ((int)(*genp - target) < 0) { }
        }
        __threadfence();
    }
    __syncthreads();
}

__device__ __forceinline__ void fc_out(const float* __restrict__ h,
                                       const float* __restrict__ fcW,
                                       const float* __restrict__ fcb,
                                       float* __restrict__ out,
                                       int n0, int td, int wid, int lane){
    for (int o = wid; o < 4*DDIM; o += 16) {
        int rr = o / DDIM, d = o - rr*DDIM;
        int n = n0 + rr;
        const float* hr = h + (size_t)n*HID;
        const float* wr = fcW + d*HID;
        float s = 0.0f;
#pragma unroll
        for (int j = 0; j < 16; ++j)
            s += __ldcg(hr + j*32 + lane) * wr[j*32 + lane];
#pragma unroll
        for (int off = 16; off; off >>= 1)
            s += __shfl_xor_sync(0xffffffffu, s, off);
        if (lane == 0)
            out[((size_t)n*TDEC + td)*DDIM + d] = sigf(s + fcb[d]);
    }
}

__global__ void __launch_bounds__(NTHREADS, 1)
lstm_kernel(const float* __restrict__ x, const float* __restrict__ W_ih,
            const float* __restrict__ W_hh, const float* __restrict__ b_ih,
            const float* __restrict__ b_hh, const float* __restrict__ fcW,
            const float* __restrict__ fcb, const float* __restrict__ h0,
            const float* __restrict__ c0, float* __restrict__ out){
    extern __shared__ char smem[];
    float* bias = (float*)(smem + SM_BIAS);
    float* wih  = (float*)(smem + SM_WIH);
    float* xp   = (float*)(smem + SM_XP);
    float* ds   = (float*)(smem + SM_DS);
    float* hfs  = (float*)(smem + SM_HF);

    const int tid = threadIdx.x, bx = blockIdx.x;
    const int mb = bx >> 5, gb = bx & 31;
    const int m0 = mb * 128;
    const int lane = tid & 31, wid = tid >> 5;
    const int wm = wid & 3, wn = wid >> 2;     // warp tile: rows wm*32, cols wn*16

    // ---- one-time init ----
    // W in B-fragment order, per-CTA slab: idx = ((kb*8 + c/8)*32 + (c&7)*4 + (k&3))*2 + ((k>>2)&1)
    {
        float* whid = g_whi + (size_t)gb*32768;
        float* wlod = g_wlo + (size_t)gb*32768;
        for (int flat = tid; flat < 64*HID; flat += NTHREADS) {
            int c = flat >> 9, k = flat & 511;
            int gr = (c & 3)*HID + gb*16 + (c >> 2);       // gate order i,f,g,o interleaved
            float wv = W_hh[(size_t)gr*HID + k];
            float hi = tf32hi(wv);
            int di = (((k>>3)*8 + (c>>3))*32 + (c&7)*4 + (k&3))*2 + ((k>>2)&1);
            whid[di] = hi; wlod[di] = wv - hi;
        }
    }
    for (int c = tid; c < 64; c += NTHREADS) {
        int gr = (c & 3)*HID + gb*16 + (c >> 2);
        bias[c] = b_ih[gr] + b_hh[gr];
        for (int d = 0; d < DDIM; ++d) wih[c*12 + d] = W_ih[gr*DDIM + d];
    }
    // initial h in both layouts (CTA handles a 1/128 slice of [512 rows x 512 units])
    for (int idx = bx*2048 + tid; idx < (bx+1)*2048; idx += NTHREADS) {
        int r = idx >> 9, j = idx & 511;
        float v = h0[j];
        g_hrm[0][(size_t)r*HID + j] = v;
        int mbb = r >> 7, mr = r & 127;
        int fi = mbb*65536 + (((j>>3)*8 + (mr>>4))*32 + (mr&7)*4 + (j&3))*4
               + ((mr>>3)&1) + 2*((j>>2)&1);
        g_hf[0][fi] = v;
    }
    float c_reg[16];
    if (tid < 128)
#pragma unroll
        for (int u = 0; u < 16; ++u) c_reg[u] = c0[gb*16 + u];
    bar_sync(4, NCTA);

    const float4* whif = (const float4*)(g_whi + (size_t)gb*32768);
    const float4* wlof = (const float4*)(g_wlo + (size_t)gb*32768);

    // ---- time loop ----
    for (int s = 0; s < NSTEPS; ++s) {
        const int rb = s & 1;
        const float4* __restrict__ hfin = (const float4*)(g_hf[rb] + mb*65536);
        const float* __restrict__ hrm_in = g_hrm[rb];
        const bool enc = (s < TENC);

        float d[2][2][4];
#pragma unroll
        for (int mt = 0; mt < 2; ++mt)
#pragma unroll
            for (int nt = 0; nt < 2; ++nt)
#pragma unroll
                for (int q = 0; q < 4; ++q) d[mt][nt][q] = 0.0f;

        // prefetch chunk 0 (all linear float4)
        float4 vA0 = __ldcg(hfin + tid);
        float4 vA1 = __ldcg(hfin + tid + 512);
        float4 vWh = __ldcg(whif + tid);
        float4 vWl = __ldcg(wlof + tid);

        if (s >= TENC + 1)
            fc_out(hrm_in, fcW, fcb, out, m0 + gb*4, s - (TENC+1), wid, lane);

        if (enc) {   // x-projection + bias -> xp[row][64]; thread: row=tid>>2, 16-col quarter
            const int xrow = tid >> 2, cb = (tid & 3)*16;
            float xv[DDIM];
#pragma unroll
            for (int dd = 0; dd < DDIM; ++dd)
                xv[dd] = __ldg(x + (size_t)(m0 + xrow)*(TENC*DDIM) + s*DDIM + dd);
            float sg[16];
#pragma unroll
            for (int c = 0; c < 16; ++c) sg[c] = bias[cb + c];
#pragma unroll
            for (int dd = 0; dd < DDIM; ++dd)
#pragma unroll
                for (int c = 0; c < 16; ++c) sg[c] += xv[dd]*wih[(cb + c)*12 + dd];
#pragma unroll
            for (int c = 0; c < 16; c += 4)
                *(float4*)(xp + xrow*XPS + cb + c) =
                    make_float4(sg[c], sg[c+1], sg[c+2], sg[c+3]);
        }

        // ---- chunk loop (KC=32, 4 k8-blocks per chunk) ----
        for (int ch = 0; ch < NCHUNK; ++ch) {
            const int b = ch & 1;
            // stage: split A hi/lo, store linear
            {
                float4 hi0 = make_float4(tf32hi(vA0.x), tf32hi(vA0.y), tf32hi(vA0.z), tf32hi(vA0.w));
                float4 hi1 = make_float4(tf32hi(vA1.x), tf32hi(vA1.y), tf32hi(vA1.z), tf32hi(vA1.w));
                ((float4*)(smem + SM_AHI(b)))[tid]       = hi0;
                ((float4*)(smem + SM_AHI(b)))[tid + 512] = hi1;
                ((float4*)(smem + SM_ALO(b)))[tid] =
                    make_float4(vA0.x-hi0.x, vA0.y-hi0.y, vA0.z-hi0.z, vA0.w-hi0.w);
                ((float4*)(smem + SM_ALO(b)))[tid + 512] =
                    make_float4(vA1.x-hi1.x, vA1.y-hi1.y, vA1.z-hi1.z, vA1.w-hi1.w);
                ((float4*)(smem + SM_WHI(b)))[tid] = vWh;
                ((float4*)(smem + SM_WLO(b)))[tid] = vWl;
            }
            __syncthreads();

            if (ch < NCHUNK-1) {
                vA0 = __ldcg(hfin + (ch+1)*1024 + tid);
                vA1 = __ldcg(hfin + (ch+1)*1024 + tid + 512);
                vWh = __ldcg(whif + (ch+1)*512 + tid);
                vWl = __ldcg(wlof + (ch+1)*512 + tid);
            }

            const float* ah = (const float*)(smem + SM_AHI(b));
            const float* al = (const float*)(smem + SM_ALO(b));
            const float* bh = (const float*)(smem + SM_WHI(b));
            const float* bl = (const float*)(smem + SM_WLO(b));
#pragma unroll
            for (int kb = 0; kb < 4; ++kb) {
                float4 Ah[2], Al[2];
#pragma unroll
                for (int mt = 0; mt < 2; ++mt) {
                    const int o = ((kb*8 + wm*2 + mt)*32 + lane)*4;
                    Ah[mt] = *(const float4*)(ah + o);
                    Al[mt] = *(const float4*)(al + o);
                }
                float2 Bh[2], Bl[2];
#pragma unroll
                for (int nt = 0; nt < 2; ++nt) {
                    const int o = ((kb*8 + wn*2 + nt)*32 + lane)*2;
                    Bh[nt] = *(const float2*)(bh + o);
                    Bl[nt] = *(const float2*)(bl + o);
                }
#pragma unroll
                for (int mt = 0; mt < 2; ++mt)
#pragma unroll
                    for (int nt = 0; nt < 2; ++nt) {
                        mma8(d[mt][nt], Ah[mt], Bh[nt]);
                        mma8(d[mt][nt], Ah[mt], Bl[nt]);
                        mma8(d[mt][nt], Al[mt], Bh[nt]);
                    }
            }
        }

        // ---- epilogue ----
        {
            const int g = lane >> 2, tq = lane & 3;
#pragma unroll
            for (int mt = 0; mt < 2; ++mt)
#pragma unroll
                for (int nt = 0; nt < 2; ++nt) {
                    const int row = wm*32 + mt*16 + g;
                    const int col = wn*16 + nt*8 + tq*2;
                    *(float2*)(ds + row*XPS + col)     = make_float2(d[mt][nt][0], d[mt][nt][1]);
                    *(float2*)(ds + (row+8)*XPS + col) = make_float2(d[mt][nt][2], d[mt][nt][3]);
                }
        }
        __syncthreads();
        if (tid < 128) {
            const int row = tid;           // mrow within mb block
            float hv[16];
#pragma unroll
            for (int u = 0; u < 16; ++u) {
                float4 gv = *(float4*)(ds + row*XPS + u*4);
                float ai, af, ag, ao;
                if (enc) {
                    float4 a = *(float4*)(xp + row*XPS + u*4);
                    ai = a.x; af = a.y; ag = a.z; ao = a.w;
                } else {
                    ai = bias[u*4]; af = bias[u*4+1]; ag = bias[u*4+2]; ao = bias[u*4+3];
                }
                float iv = gv.x + ai, fv = gv.y + af, gg = gv.z + ag, ov = gv.w + ao;
                float cn = sigf(fv)*c_reg[u] + sigf(iv)*tanhf(gg);
                c_reg[u] = cn;
                hv[u] = sigf(ov)*tanhf(cn);
            }
            // row-major store for FC head
            float* hw = g_hrm[rb ^ 1] + (size_t)(m0 + row)*HID + gb*16;
#pragma unroll
            for (int u = 0; u < 16; u += 4)
                *(float4*)(hw + u) = make_float4(hv[u], hv[u+1], hv[u+2], hv[u+3]);
            // fragment-order scatter into smem staging (CTA-relative slab 2048 floats)
            const int rbit = (row >> 3) & 1, mt = row >> 4, l4 = (row & 7)*4;
#pragma unroll
            for (int jj = 0; jj < 16; ++jj) {
                int fi = (((jj>>3)*8 + mt)*32 + l4 + (jj&3))*4 + rbit + 2*((jj>>2)&1);
                hfs[fi] = hv[jj];
            }
        }
        __syncthreads();
        // linear copy staging -> global fragment-ordered h
        ((float4*)(g_hf[rb ^ 1] + mb*65536 + gb*2048))[tid] = ((const float4*)hfs)[tid];
        bar_sync(mb, 32);
    }

    fc_out(g_hrm[NSTEPS & 1], fcW, fcb, out, m0 + gb*4, TDEC - 1, wid, lane);
}

extern "C" void kernel_launch(void* const* d_in, const int* in_sizes, int n_in,
                              void* d_out, int out_size){
    (void)in_sizes; (void)n_in; (void)out_size;
    cudaFuncSetAttribute(lstm_kernel, cudaFuncAttributeMaxDynamicSharedMemorySize,
                         SMEM_BYTES);
    lstm_kernel<<<NCTA, NTHREADS, SMEM_BYTES>>>(
        (const float*)d_in[0], (const float*)d_in[1], (const float*)d_in[2],
        (const float*)d_in[3], (const float*)d_in[4], (const float*)d_in[5],
        (const float*)d_in[6], (const float*)d_in[7], (const float*)d_in[8],
        (float*)d_out);
}

// round 11
// speedup vs baseline: 2.4274x; 1.3339x over previous
#include <cuda_runtime.h>
#include <cuda_bf16.h>
#include <cstdint>

#define NBATCH 512
#define HID 512
#define DDIM 9
#define TENC 257
#define TDEC 256
#define NSTEPS 513
#define NCHUNK 16
#define NCTA 128
#define NTHREADS 512
#define XPS 68

// smem layout (bytes)
#define SM_BIAS 0
#define SM_WIH  256
#define SM_XP   3584
#define SM_DS   (SM_XP + 128*XPS*4)   // 38400
#define SM_HFH  (SM_DS + 128*XPS*4)   // 73216 : 4KB bf16-hi staging
#define SM_HFM  (SM_HFH + 4096)       // 77312 : 4KB bf16-mid staging
#define SM_B0   81920
#define ABSZ 8192                     // A term buffer (128x32 bf16)
#define WBSZ 8192                     // W buffer (64x32 x 2 terms bf16, interleaved)
#define BUFSZ (2*ABSZ + WBSZ)         // 24576
#define SM_AHI(b) (SM_B0 + (b)*BUFSZ)
#define SM_AMI(b) (SM_AHI(b) + ABSZ)
#define SM_WB(b)  (SM_AMI(b) + ABSZ)
#define SMEM_BYTES (SM_B0 + 2*BUFSZ)  // 131072

typedef unsigned short ushort_t;

// fragment-packed bf16 hidden state: per time-buf, per mb slab 65536 units
__device__ __align__(16) ushort_t g_habf[2][4*65536];
__device__ __align__(16) ushort_t g_hmbf[2][4*65536];
__device__ __align__(16) float    g_hrm[2][NBATCH*HID];   // row-major fp32 for FC head
// W packed: per gb slab 65536 ushort (hi/mid interleaved per 16B lane-chunk)
__device__ __align__(16) ushort_t g_wpk[32*65536];
__device__ unsigned s_cnt[5*32];
__device__ unsigned s_gen[5*32];

__device__ __forceinline__ float sigf(float x){ return 1.0f/(1.0f+__expf(-x)); }
__device__ __forceinline__ ushort_t bf16u(float v){
    __nv_bfloat16 b = __float2bfloat16_rn(v);
    return *(ushort_t*)&b;
}
__device__ __forceinline__ float bf16f(ushort_t u){
    __nv_bfloat16 b = *(__nv_bfloat16*)&u;
    return __bfloat162float(b);
}
__device__ __forceinline__ void mma16(float* d, const uint4& a, uint32_t b0, uint32_t b1){
    asm volatile("mma.sync.aligned.m16n8k16.row.col.f32.bf16.bf16.f32 "
        "{%0,%1,%2,%3}, {%4,%5,%6,%7}, {%8,%9}, {%0,%1,%2,%3};"
        : "+f"(d[0]), "+f"(d[1]), "+f"(d[2]), "+f"(d[3])
        : "r"(a.x), "r"(a.y), "r"(a.z), "r"(a.w), "r"(b0), "r"(b1));
}

__device__ __forceinline__ void bar_sync(int g, unsigned count){
    __syncthreads();
    if (threadIdx.x == 0) {
        __threadfence();
        volatile unsigned* genp = &s_gen[g*32];
        unsigned target = *genp + 1u;
        if (atomicAdd(&s_cnt[g*32], 1u) == count - 1u) {
            atomicExch(&s_cnt[g*32], 0u);
            __threadfence();
            atomicExch((unsigned*)&s_gen[g*32], target);
        } else {
            while ((int)(*genp - target) < 0) { }
        }
        __threadfence();
    }
    __syncthreads();
}

__device__ __forceinline__ void fc_out(const float* __restrict__ h,
                                       const float* __restrict__ fcW,
                                       const float* __restrict__ fcb,
                                       float* __restrict__ out,
                                       int n0, int td, int wid, int lane){
    for (int o = wid; o < 4*DDIM; o += 16) {
        int rr = o / DDIM, d = o - rr*DDIM;
        int n = n0 + rr;
        const float* hr = h + (size_t)n*HID;
        const float* wr = fcW + d*HID;
        float s = 0.0f;
#pragma unroll
        for (int j = 0; j < 16; ++j)
            s += __ldcg(hr + j*32 + lane) * wr[j*32 + lane];
#pragma unroll
        for (int off = 16; off; off >>= 1)
            s += __shfl_xor_sync(0xffffffffu, s, off);
        if (lane == 0)
            out[((size_t)n*TDEC + td)*DDIM + d] = sigf(s + fcb[d]);
    }
}

__global__ void __launch_bounds__(NTHREADS, 1)
lstm_kernel(const float* __restrict__ x, const float* __restrict__ W_ih,
            const float* __restrict__ W_hh, const float* __restrict__ b_ih,
            const float* __restrict__ b_hh, const float* __restrict__ fcW,
            const float* __restrict__ fcb, const float* __restrict__ h0,
            const float* __restrict__ c0, float* __restrict__ out){
    extern __shared__ char smem[];
    float* bias = (float*)(smem + SM_BIAS);
    float* wih  = (float*)(smem + SM_WIH);
    float* xp   = (float*)(smem + SM_XP);
    float* ds   = (float*)(smem + SM_DS);
    ushort_t* hfh = (ushort_t*)(smem + SM_HFH);
    ushort_t* hfm = (ushort_t*)(smem + SM_HFM);

    const int tid = threadIdx.x, bx = blockIdx.x;
    const int mb = bx >> 5, gb = bx & 31;
    const int m0 = mb * 128;
    const int lane = tid & 31, wid = tid >> 5;
    const int wm = wid & 3, wn = wid >> 2;     // warp tile: rows wm*32, cols wn*16

    // ---- one-time init ----
    // W split into bf16 hi/mid, fragment-packed, hi/mid interleaved per 16B lane-chunk
    {
        ushort_t* wd = g_wpk + (size_t)gb*65536;
        for (int flat = tid; flat < 64*HID; flat += NTHREADS) {
            int c = flat >> 9, k = flat & 511;
            int gr = (c & 3)*HID + gb*16 + (c >> 2);   // gate order i,f,g,o interleaved
            float wv = W_hh[(size_t)gr*HID + k];
            ushort_t hi = bf16u(wv);
            ushort_t mi = bf16u(wv - bf16f(hi));
            int ci = ((k>>4)*8 + (c>>3))*32 + (c&7)*4 + ((k&7)>>1);
            int pos = 2*((k>>3)&1) + (k&1);
            wd[ci*8 + pos]     = hi;
            wd[ci*8 + 4 + pos] = mi;
        }
    }
    for (int c = tid; c < 64; c += NTHREADS) {
        int gr = (c & 3)*HID + gb*16 + (c >> 2);
        bias[c] = b_ih[gr] + b_hh[gr];
        for (int d = 0; d < DDIM; ++d) wih[c*12 + d] = W_ih[gr*DDIM + d];
    }
    // initial h in all layouts (CTA covers 1/128 of 512x512)
    for (int idx = bx*2048 + tid; idx < (bx+1)*2048; idx += NTHREADS) {
        int r = idx >> 9, j = idx & 511;
        float v = h0[j];
        g_hrm[0][(size_t)r*HID + j] = v;
        int mbb = r >> 7, m = r & 127;
        int ci = ((j>>4)*8 + (m>>4))*32 + (m&7)*4 + ((j&7)>>1);
        int pos = 2*((m>>3)&1) + 4*((j>>3)&1) + (j&1);
        ushort_t hi = bf16u(v);
        g_habf[0][mbb*65536 + ci*8 + pos] = hi;
        g_hmbf[0][mbb*65536 + ci*8 + pos] = bf16u(v - bf16f(hi));
    }
    float c_reg[16];
    if (tid < 128)
#pragma unroll
        for (int u = 0; u < 16; ++u) c_reg[u] = c0[gb*16 + u];
    bar_sync(4, NCTA);

    const uint4* wsrc = (const uint4*)(g_wpk + (size_t)gb*65536);

    // ---- time loop ----
    for (int s = 0; s < NSTEPS; ++s) {
        const int rb = s & 1;
        const uint4* __restrict__ hsrc = (const uint4*)(g_habf[rb] + mb*65536);
        const uint4* __restrict__ msrc = (const uint4*)(g_hmbf[rb] + mb*65536);
        const float* __restrict__ hrm_in = g_hrm[rb];
        const bool enc = (s < TENC);

        float d[2][2][4];
#pragma unroll
        for (int mt = 0; mt < 2; ++mt)
#pragma unroll
            for (int nt = 0; nt < 2; ++nt)
#pragma unroll
                for (int q = 0; q < 4; ++q) d[mt][nt][q] = 0.0f;

        // prefetch chunk 0 (linear uint4)
        uint4 vh = __ldcg(hsrc + tid);
        uint4 vm = __ldcg(msrc + tid);
        uint4 vw = __ldcg(wsrc + tid);

        if (s >= TENC + 1)
            fc_out(hrm_in, fcW, fcb, out, m0 + gb*4, s - (TENC+1), wid, lane);

        if (enc) {   // x-projection + bias -> xp[row][64]
            const int xrow = tid >> 2, cb = (tid & 3)*16;
            float xv[DDIM];
#pragma unroll
            for (int dd = 0; dd < DDIM; ++dd)
                xv[dd] = __ldg(x + (size_t)(m0 + xrow)*(TENC*DDIM) + s*DDIM + dd);
            float sg[16];
#pragma unroll
            for (int c = 0; c < 16; ++c) sg[c] = bias[cb + c];
#pragma unroll
            for (int dd = 0; dd < DDIM; ++dd)
#pragma unroll
                for (int c = 0; c < 16; ++c) sg[c] += xv[dd]*wih[(cb + c)*12 + dd];
#pragma unroll
            for (int c = 0; c < 16; c += 4)
                *(float4*)(xp + xrow*XPS + cb + c) =
                    make_float4(sg[c], sg[c+1], sg[c+2], sg[c+3]);
        }

        // ---- chunk loop (K=32 per chunk = 2 k16 blocks) ----
        for (int ch = 0; ch < NCHUNK; ++ch) {
            const int b = ch & 1;
            ((uint4*)(smem + SM_AHI(b)))[tid] = vh;
            ((uint4*)(smem + SM_AMI(b)))[tid] = vm;
            ((uint4*)(smem + SM_WB(b)))[tid]  = vw;
            __syncthreads();

            if (ch < NCHUNK-1) {
                vh = __ldcg(hsrc + (ch+1)*512 + tid);
                vm = __ldcg(msrc + (ch+1)*512 + tid);
                vw = __ldcg(wsrc + (ch+1)*512 + tid);
            }

            const uint4* ah4 = (const uint4*)(smem + SM_AHI(b));
            const uint4* am4 = (const uint4*)(smem + SM_AMI(b));
            const uint4* wb4 = (const uint4*)(smem + SM_WB(b));
#pragma unroll
            for (int kb = 0; kb < 2; ++kb) {
                uint4 Ah[2], Am[2], Bv[2];
#pragma unroll
                for (int mt = 0; mt < 2; ++mt) {
                    const int o = (kb*8 + wm*2 + mt)*32 + lane;
                    Ah[mt] = ah4[o]; Am[mt] = am4[o];
                }
#pragma unroll
                for (int nt = 0; nt < 2; ++nt)
                    Bv[nt] = wb4[(kb*8 + wn*2 + nt)*32 + lane];
#pragma unroll
                for (int mt = 0; mt < 2; ++mt)
#pragma unroll
                    for (int nt = 0; nt < 2; ++nt) {
                        mma16(d[mt][nt], Ah[mt], Bv[nt].x, Bv[nt].y);  // hi*hi
                        mma16(d[mt][nt], Ah[mt], Bv[nt].z, Bv[nt].w);  // hi*mid
                        mma16(d[mt][nt], Am[mt], Bv[nt].x, Bv[nt].y);  // mid*hi
                        mma16(d[mt][nt], Am[mt], Bv[nt].z, Bv[nt].w);  // mid*mid
                    }
            }
        }

        // ---- epilogue ----
        {
            const int g = lane >> 2, tq = lane & 3;
#pragma unroll
            for (int mt = 0; mt < 2; ++mt)
#pragma unroll
                for (int nt = 0; nt < 2; ++nt) {
                    const int row = wm*32 + mt*16 + g;
                    const int col = wn*16 + nt*8 + tq*2;
                    *(float2*)(ds + row*XPS + col)     = make_float2(d[mt][nt][0], d[mt][nt][1]);
                    *(float2*)(ds + (row+8)*XPS + col) = make_float2(d[mt][nt][2], d[mt][nt][3]);
                }
        }
        __syncthreads();
        if (tid < 128) {
            const int row = tid;
            float hv[16];
#pragma unroll
            for (int u = 0; u < 16; ++u) {
                float4 gv = *(float4*)(ds + row*XPS + u*4);
                float ai, af, ag, ao;
                if (enc) {
                    float4 a = *(float4*)(xp + row*XPS + u*4);
                    ai = a.x; af = a.y; ag = a.z; ao = a.w;
                } else {
                    ai = bias[u*4]; af = bias[u*4+1]; ag = bias[u*4+2]; ao = bias[u*4+3];
                }
                float iv = gv.x + ai, fv = gv.y + af, gg = gv.z + ag, ov = gv.w + ao;
                float cn = sigf(fv)*c_reg[u] + sigf(iv)*tanhf(gg);
                c_reg[u] = cn;
                hv[u] = sigf(ov)*tanhf(cn);
            }
            // row-major fp32 for FC head
            float* hw = g_hrm[rb ^ 1] + (size_t)(m0 + row)*HID + gb*16;
#pragma unroll
            for (int u = 0; u < 16; u += 4)
                *(float4*)(hw + u) = make_float4(hv[u], hv[u+1], hv[u+2], hv[u+3]);
            // bf16 split, fragment-order scatter into smem staging (2048 units)
#pragma unroll
            for (int u = 0; u < 16; ++u) {
                int ci = (row>>4)*32 + (row&7)*4 + ((u&7)>>1);
                int pos = 2*((row>>3)&1) + 4*((u>>3)&1) + (u&1);
                ushort_t hi = bf16u(hv[u]);
                hfh[ci*8 + pos] = hi;
                hfm[ci*8 + pos] = bf16u(hv[u] - bf16f(hi));
            }
        }
        __syncthreads();
        // linear copy staging -> global fragment-packed h (hi: threads 0-255, mid: 256-511)
        if (tid < 256)
            ((uint4*)(g_habf[rb ^ 1] + mb*65536))[gb*256 + tid] = ((const uint4*)hfh)[tid];
        else
            ((uint4*)(g_hmbf[rb ^ 1] + mb*65536))[gb*256 + tid - 256] = ((const uint4*)hfm)[tid - 256];
        bar_sync(mb, 32);
    }

    fc_out(g_hrm[NSTEPS & 1], fcW, fcb, out, m0 + gb*4, TDEC - 1, wid, lane);
}

extern "C" void kernel_launch(void* const* d_in, const int* in_sizes, int n_in,
                              void* d_out, int out_size){
    (void)in_sizes; (void)n_in; (void)out_size;
    cudaFuncSetAttribute(lstm_kernel, cudaFuncAttributeMaxDynamicSharedMemorySize,
                         SMEM_BYTES);
    lstm_kernel<<<NCTA, NTHREADS, SMEM_BYTES>>>(
        (const float*)d_in[0], (const float*)d_in[1], (const float*)d_in[2],
        (const float*)d_in[3], (const float*)d_in[4], (const float*)d_in[5],
        (const float*)d_in[6], (const float*)d_in[7], (const float*)d_in[8],
        (float*)d_out);
}

// round 12
// speedup vs baseline: 2.9473x; 1.2142x over previous
#include <cuda_runtime.h>
#include <cuda_bf16.h>
#include <cstdint>

#define NBATCH 512
#define HID 512
#define DDIM 9
#define TENC 257
#define TDEC 256
#define NSTEPS 513
#define NCTA 128
#define NTHREADS 512
#define XPS 68
#define DEPTH 4

// smem layout (bytes)
#define SM_BIAS 0
#define SM_WIH  256
#define SM_XP   3584
#define SM_DS   (SM_XP + 128*XPS*4)   // 38400
#define SM_HFH  (SM_DS + 128*XPS*4)   // 73216
#define SM_HFM  (SM_HFH + 4096)       // 77312
#define SM_W    81408                 // 128KB persistent packed W
#define SMEM_BYTES (SM_W + 131072)    // 212480

typedef unsigned short ushort_t;

// fragment-packed bf16 hidden state (hi & mid terms), per time-buffer, per mb slab
__device__ __align__(16) ushort_t g_habf[2][4*65536];
__device__ __align__(16) ushort_t g_hmbf[2][4*65536];
__device__ __align__(16) float    g_hrm[2][NBATCH*HID];   // row-major fp32 for FC head
__device__ unsigned s_cnt[5*32];
__device__ unsigned s_gen[5*32];

__device__ __forceinline__ float sigf(float x){ return 1.0f/(1.0f+__expf(-x)); }
__device__ __forceinline__ ushort_t bf16u(float v){
    __nv_bfloat16 b = __float2bfloat16_rn(v);
    return *(ushort_t*)&b;
}
__device__ __forceinline__ float bf16f(ushort_t u){
    __nv_bfloat16 b = *(__nv_bfloat16*)&u;
    return __bfloat162float(b);
}
__device__ __forceinline__ void mma16(float* d, const uint4& a, uint32_t b0, uint32_t b1){
    asm volatile("mma.sync.aligned.m16n8k16.row.col.f32.bf16.bf16.f32 "
        "{%0,%1,%2,%3}, {%4,%5,%6,%7}, {%8,%9}, {%0,%1,%2,%3};"
        : "+f"(d[0]), "+f"(d[1]), "+f"(d[2]), "+f"(d[3])
        : "r"(a.x), "r"(a.y), "r"(a.z), "r"(a.w), "r"(b0), "r"(b1));
}

__device__ __forceinline__ void bar_sync(int g, unsigned count){
    __syncthreads();
    if (threadIdx.x == 0) {
        __threadfence();
        volatile unsigned* genp = &s_gen[g*32];
        unsigned target = *genp + 1u;
        if (atomicAdd(&s_cnt[g*32], 1u) == count - 1u) {
            atomicExch(&s_cnt[g*32], 0u);
            __threadfence();
            atomicExch((unsigned*)&s_gen[g*32], target);
        } else {
            while ((int)(*genp - target) < 0) { }
        }
        __threadfence();
    }
    __syncthreads();
}

__device__ __forceinline__ void fc_out(const float* __restrict__ h,
                                       const float* __restrict__ fcW,
                                       const float* __restrict__ fcb,
                                       float* __restrict__ out,
                                       int n0, int td, int wid, int lane){
    for (int o = wid; o < 4*DDIM; o += 16) {
        int rr = o / DDIM, d = o - rr*DDIM;
        int n = n0 + rr;
        const float* hr = h + (size_t)n*HID;
        const float* wr = fcW + d*HID;
        float s = 0.0f;
#pragma unroll
        for (int j = 0; j < 16; ++j)
            s += __ldcg(hr + j*32 + lane) * wr[j*32 + lane];
#pragma unroll
        for (int off = 16; off; off >>= 1)
            s += __shfl_xor_sync(0xffffffffu, s, off);
        if (lane == 0)
            out[((size_t)n*TDEC + td)*DDIM + d] = sigf(s + fcb[d]);
    }
}

__global__ void __launch_bounds__(NTHREADS, 1)
lstm_kernel(const float* __restrict__ x, const float* __restrict__ W_ih,
            const float* __restrict__ W_hh, const float* __restrict__ b_ih,
            const float* __restrict__ b_hh, const float* __restrict__ fcW,
            const float* __restrict__ fcb, const float* __restrict__ h0,
            const float* __restrict__ c0, float* __restrict__ out){
    extern __shared__ char smem[];
    float* bias = (float*)(smem + SM_BIAS);
    float* wih  = (float*)(smem + SM_WIH);
    float* xp   = (float*)(smem + SM_XP);
    float* ds   = (float*)(smem + SM_DS);
    ushort_t* hfh = (ushort_t*)(smem + SM_HFH);
    ushort_t* hfm = (ushort_t*)(smem + SM_HFM);
    ushort_t* wsm = (ushort_t*)(smem + SM_W);
    const uint4* wsm4 = (const uint4*)(smem + SM_W);

    const int tid = threadIdx.x, bx = blockIdx.x;
    const int mb = bx >> 5, gb = bx & 31;
    const int m0 = mb * 128;
    const int lane = tid & 31, wid = tid >> 5;
    const int wm = wid & 3, wn = wid >> 2;     // warp tile: rows wm*32, cols wn*16

    // ---- one-time init ----
    // W split bf16 hi/mid, fragment-packed straight into persistent smem
    for (int flat = tid; flat < 64*HID; flat += NTHREADS) {
        int c = flat >> 9, k = flat & 511;
        int gr = (c & 3)*HID + gb*16 + (c >> 2);      // gate order i,f,g,o interleaved
        float wv = W_hh[(size_t)gr*HID + k];
        ushort_t hi = bf16u(wv);
        ushort_t mi = bf16u(wv - bf16f(hi));
        int ci = (k>>4)*256 + (c>>3)*32 + (c&7)*4 + ((k&7)>>1);
        int pos = 2*((k>>3)&1) + (k&1);
        wsm[ci*8 + pos]     = hi;
        wsm[ci*8 + 4 + pos] = mi;
    }
    for (int c = tid; c < 64; c += NTHREADS) {
        int gr = (c & 3)*HID + gb*16 + (c >> 2);
        bias[c] = b_ih[gr] + b_hh[gr];
        for (int d = 0; d < DDIM; ++d) wih[c*12 + d] = W_ih[gr*DDIM + d];
    }
    // initial h in all layouts (CTA covers 1/128 of 512x512)
    for (int idx = bx*2048 + tid; idx < (bx+1)*2048; idx += NTHREADS) {
        int r = idx >> 9, j = idx & 511;
        float v = h0[j];
        g_hrm[0][(size_t)r*HID + j] = v;
        int mbb = r >> 7, m = r & 127;
        int ci = (j>>4)*256 + (m>>4)*32 + (m&7)*4 + ((j&7)>>1);
        int pos = 2*((m>>3)&1) + 4*((j>>3)&1) + (j&1);
        ushort_t hi = bf16u(v);
        g_habf[0][mbb*65536 + ci*8 + pos] = hi;
        g_hmbf[0][mbb*65536 + ci*8 + pos] = bf16u(v - bf16f(hi));
    }
    float c_reg[16];
    if (tid < 128)
#pragma unroll
        for (int u = 0; u < 16; ++u) c_reg[u] = c0[gb*16 + u];
    bar_sync(4, NCTA);

    // per-warp fragment offsets (uint4 index within a kb8 slab of 256)
    const int aoff0 = (wm*2 + 0)*32 + lane;
    const int aoff1 = (wm*2 + 1)*32 + lane;
    const int boff0 = (wn*2 + 0)*32 + lane;
    const int boff1 = (wn*2 + 1)*32 + lane;

    // ---- time loop ----
    for (int s = 0; s < NSTEPS; ++s) {
        const int rb = s & 1;
        const uint4* __restrict__ hsrc = (const uint4*)(g_habf[rb] + mb*65536);
        const uint4* __restrict__ msrc = (const uint4*)(g_hmbf[rb] + mb*65536);
        const float* __restrict__ hrm_in = g_hrm[rb];
        const bool enc = (s < TENC);

        float d[2][2][4];
#pragma unroll
        for (int mt = 0; mt < 2; ++mt)
#pragma unroll
            for (int nt = 0; nt < 2; ++nt)
#pragma unroll
                for (int q = 0; q < 4; ++q) d[mt][nt][q] = 0.0f;

        // A pipeline prologue
        uint4 Ah[DEPTH][2], Am[DEPTH][2];
#pragma unroll
        for (int p = 0; p < DEPTH; ++p) {
            Ah[p][0] = __ldcg(hsrc + p*256 + aoff0);
            Ah[p][1] = __ldcg(hsrc + p*256 + aoff1);
            Am[p][0] = __ldcg(msrc + p*256 + aoff0);
            Am[p][1] = __ldcg(msrc + p*256 + aoff1);
        }

        if (s >= TENC + 1)
            fc_out(hrm_in, fcW, fcb, out, m0 + gb*4, s - (TENC+1), wid, lane);

        if (enc) {   // x-projection + bias -> xp[row][64]
            const int xrow = tid >> 2, cb = (tid & 3)*16;
            float xv[DDIM];
#pragma unroll
            for (int dd = 0; dd < DDIM; ++dd)
                xv[dd] = __ldg(x + (size_t)(m0 + xrow)*(TENC*DDIM) + s*DDIM + dd);
            float sg[16];
#pragma unroll
            for (int c = 0; c < 16; ++c) sg[c] = bias[cb + c];
#pragma unroll
            for (int dd = 0; dd < DDIM; ++dd)
#pragma unroll
                for (int c = 0; c < 16; ++c) sg[c] += xv[dd]*wih[(cb + c)*12 + dd];
#pragma unroll
            for (int c = 0; c < 16; c += 4)
                *(float4*)(xp + xrow*XPS + cb + c) =
                    make_float4(sg[c], sg[c+1], sg[c+2], sg[c+3]);
        }

        // ---- GEMM: 32 k16-blocks, sync-free, B from persistent smem ----
#pragma unroll
        for (int kb = 0; kb < 32; ++kb) {
            const int slot = kb & (DEPTH - 1);
            uint4 B0 = wsm4[kb*256 + boff0];
            uint4 B1 = wsm4[kb*256 + boff1];
            // 3-pass Dekker: hi*hi, hi*mid, mid*hi
            mma16(d[0][0], Ah[slot][0], B0.x, B0.y);
            mma16(d[0][1], Ah[slot][0], B1.x, B1.y);
            mma16(d[1][0], Ah[slot][1], B0.x, B0.y);
            mma16(d[1][1], Ah[slot][1], B1.x, B1.y);
            mma16(d[0][0], Ah[slot][0], B0.z, B0.w);
            mma16(d[0][1], Ah[slot][0], B1.z, B1.w);
            mma16(d[1][0], Ah[slot][1], B0.z, B0.w);
            mma16(d[1][1], Ah[slot][1], B1.z, B1.w);
            mma16(d[0][0], Am[slot][0], B0.x, B0.y);
            mma16(d[0][1], Am[slot][0], B1.x, B1.y);
            mma16(d[1][0], Am[slot][1], B0.x, B0.y);
            mma16(d[1][1], Am[slot][1], B1.x, B1.y);
            if (kb + DEPTH < 32) {
                Ah[slot][0] = __ldcg(hsrc + (kb+DEPTH)*256 + aoff0);
                Ah[slot][1] = __ldcg(hsrc + (kb+DEPTH)*256 + aoff1);
                Am[slot][0] = __ldcg(msrc + (kb+DEPTH)*256 + aoff0);
                Am[slot][1] = __ldcg(msrc + (kb+DEPTH)*256 + aoff1);
            }
        }

        // ---- epilogue ----
        {
            const int g = lane >> 2, tq = lane & 3;
#pragma unroll
            for (int mt = 0; mt < 2; ++mt)
#pragma unroll
                for (int nt = 0; nt < 2; ++nt) {
                    const int row = wm*32 + mt*16 + g;
                    const int col = wn*16 + nt*8 + tq*2;
                    *(float2*)(ds + row*XPS + col)     = make_float2(d[mt][nt][0], d[mt][nt][1]);
                    *(float2*)(ds + (row+8)*XPS + col) = make_float2(d[mt][nt][2], d[mt][nt][3]);
                }
        }
        __syncthreads();
        if (tid < 128) {
            const int row = tid;
            float hv[16];
#pragma unroll
            for (int u = 0; u < 16; ++u) {
                float4 gv = *(float4*)(ds + row*XPS + u*4);
                float ai, af, ag, ao;
                if (enc) {
                    float4 a = *(float4*)(xp + row*XPS + u*4);
                    ai = a.x; af = a.y; ag = a.z; ao = a.w;
                } else {
                    ai = bias[u*4]; af = bias[u*4+1]; ag = bias[u*4+2]; ao = bias[u*4+3];
                }
                float iv = gv.x + ai, fv = gv.y + af, gg = gv.z + ag, ov = gv.w + ao;
                float cn = sigf(fv)*c_reg[u] + sigf(iv)*tanhf(gg);
                c_reg[u] = cn;
                hv[u] = sigf(ov)*tanhf(cn);
            }
            float* hw = g_hrm[rb ^ 1] + (size_t)(m0 + row)*HID + gb*16;
#pragma unroll
            for (int u = 0; u < 16; u += 4)
                *(float4*)(hw + u) = make_float4(hv[u], hv[u+1], hv[u+2], hv[u+3]);
            // bf16 split, fragment-order scatter into smem staging
#pragma unroll
            for (int u = 0; u < 16; ++u) {
                int ci = (row>>4)*32 + (row&7)*4 + ((u&7)>>1);
                int pos = 2*((row>>3)&1) + 4*((u>>3)&1) + (u&1);
                ushort_t hi = bf16u(hv[u]);
                hfh[ci*8 + pos] = hi;
                hfm[ci*8 + pos] = bf16u(hv[u] - bf16f(hi));
            }
        }
        __syncthreads();
        // linear copy staging -> global fragment-packed h
        if (tid < 256)
            ((uint4*)(g_habf[rb ^ 1] + mb*65536))[gb*256 + tid] = ((const uint4*)hfh)[tid];
        else
            ((uint4*)(g_hmbf[rb ^ 1] + mb*65536))[gb*256 + tid - 256] = ((const uint4*)hfm)[tid - 256];
        bar_sync(mb, 32);
    }

    fc_out(g_hrm[NSTEPS & 1], fcW, fcb, out, m0 + gb*4, TDEC - 1, wid, lane);
}

extern "C" void kernel_launch(void* const* d_in, const int* in_sizes, int n_in,
                              void* d_out, int out_size){
    (void)in_sizes; (void)n_in; (void)out_size;
    cudaFuncSetAttribute(lstm_kernel, cudaFuncAttributeMaxDynamicSharedMemorySize,
                         SMEM_BYTES);
    lstm_kernel<<<NCTA, NTHREADS, SMEM_BYTES>>>(
        (const float*)d_in[0], (const float*)d_in[1], (const float*)d_in[2],
        (const float*)d_in[3], (const float*)d_in[4], (const float*)d_in[5],
        (const float*)d_in[6], (const float*)d_in[7], (const float*)d_in[8],
        (float*)d_out);
}

// round 13
// speedup vs baseline: 3.9067x; 1.3255x over previous
#include <cuda_runtime.h>
#include <cuda_bf16.h>
#include <cstdint>

#define NBATCH 512
#define HID 512
#define DDIM 9
#define TENC 257
#define TDEC 256
#define NSTEPS 513
#define NCTA 128
#define NTHREADS 512
#define XPS 68
#define DEPTH 4

// smem layout (bytes)
#define SM_BIAS 0
#define SM_WIH  256
#define SM_XP   3584
#define SM_DS   (SM_XP + 128*XPS*4)   // 38400
#define SM_HFH  (SM_DS + 128*XPS*4)   // 73216
#define SM_HFM  (SM_HFH + 4096)       // 77312
#define SM_W    81408                 // 128KB persistent packed W
#define SMEM_BYTES (SM_W + 131072)    // 212480

typedef unsigned short ushort_t;

// fragment-packed bf16 hidden state (hi & mid terms), per time-buffer, per mb slab
__device__ __align__(16) ushort_t g_habf[2][4*65536];
__device__ __align__(16) ushort_t g_hmbf[2][4*65536];
__device__ __align__(16) float    g_hrm[2][NBATCH*HID];   // row-major fp32 for FC head
__device__ unsigned s_cnt[5*32];
__device__ unsigned s_gen[5*32];

__device__ __forceinline__ float sigf(float x){ return 1.0f/(1.0f+__expf(-x)); }
__device__ __forceinline__ ushort_t bf16u(float v){
    __nv_bfloat16 b = __float2bfloat16_rn(v);
    return *(ushort_t*)&b;
}
__device__ __forceinline__ float bf16f(ushort_t u){
    __nv_bfloat16 b = *(__nv_bfloat16*)&u;
    return __bfloat162float(b);
}
__device__ __forceinline__ void mma16(float* d, const uint4& a, uint32_t b0, uint32_t b1){
    asm volatile("mma.sync.aligned.m16n8k16.row.col.f32.bf16.bf16.f32 "
        "{%0,%1,%2,%3}, {%4,%5,%6,%7}, {%8,%9}, {%0,%1,%2,%3};"
        : "+f"(d[0]), "+f"(d[1]), "+f"(d[2]), "+f"(d[3])
        : "r"(a.x), "r"(a.y), "r"(a.z), "r"(a.w), "r"(b0), "r"(b1));
}

__device__ __forceinline__ void bar_sync(int g, unsigned count){
    __syncthreads();
    if (threadIdx.x == 0) {
        __threadfence();
        volatile unsigned* genp = &s_gen[g*32];
        unsigned target = *genp + 1u;
        if (atomicAdd(&s_cnt[g*32], 1u) == count - 1u) {
            atomicExch(&s_cnt[g*32], 0u);
            __threadfence();
            atomicExch((unsigned*)&s_gen[g*32], target);
        } else {
            while ((int)(*genp - target) < 0) { }
        }
        __threadfence();
    }
    __syncthreads();
}

__device__ __forceinline__ void fc_out(const float* __restrict__ h,
                                       const float* __restrict__ fcW,
                                       const float* __restrict__ fcb,
                                       float* __restrict__ out,
                                       int n0, int td, int wid, int lane){
    for (int o = wid; o < 4*DDIM; o += 16) {
        int rr = o / DDIM, d = o - rr*DDIM;
        int n = n0 + rr;
        const float* hr = h + (size_t)n*HID;
        const float* wr = fcW + d*HID;
        float s = 0.0f;
#pragma unroll
        for (int j = 0; j < 16; ++j)
            s += __ldcg(hr + j*32 + lane) * wr[j*32 + lane];
#pragma unroll
        for (int off = 16; off; off >>= 1)
            s += __shfl_xor_sync(0xffffffffu, s, off);
        if (lane == 0)
            out[((size_t)n*TDEC + td)*DDIM + d] = sigf(s + fcb[d]);
    }
}

__global__ void __launch_bounds__(NTHREADS, 1)
lstm_kernel(const float* __restrict__ x, const float* __restrict__ W_ih,
            const float* __restrict__ W_hh, const float* __restrict__ b_ih,
            const float* __restrict__ b_hh, const float* __restrict__ fcW,
            const float* __restrict__ fcb, const float* __restrict__ h0,
            const float* __restrict__ c0, float* __restrict__ out){
    extern __shared__ char smem[];
    float* bias = (float*)(smem + SM_BIAS);
    float* wih  = (float*)(smem + SM_WIH);
    float* xp   = (float*)(smem + SM_XP);
    float* ds   = (float*)(smem + SM_DS);
    ushort_t* hfh = (ushort_t*)(smem + SM_HFH);
    ushort_t* hfm = (ushort_t*)(smem + SM_HFM);
    ushort_t* wsm = (ushort_t*)(smem + SM_W);
    const uint4* wsm4 = (const uint4*)(smem + SM_W);

    const int tid = threadIdx.x, bx = blockIdx.x;
    const int mb = bx >> 5, gb = bx & 31;
    const int m0 = mb * 128;
    const int lane = tid & 31, wid = tid >> 5;
    const int wm = wid & 7, wn = wid >> 3;     // warp tile: rows wm*16, cols wn*32

    // ---- one-time init ----
    // W split bf16 hi/mid, fragment-packed into persistent smem
    for (int flat = tid; flat < 64*HID; flat += NTHREADS) {
        int c = flat >> 9, k = flat & 511;
        int gr = (c & 3)*HID + gb*16 + (c >> 2);      // gate order i,f,g,o interleaved
        float wv = W_hh[(size_t)gr*HID + k];
        ushort_t hi = bf16u(wv);
        ushort_t mi = bf16u(wv - bf16f(hi));
        int ci = (k>>4)*256 + (c>>3)*32 + (c&7)*4 + ((k&7)>>1);
        int pos = 2*((k>>3)&1) + (k&1);
        wsm[ci*8 + pos]     = hi;
        wsm[ci*8 + 4 + pos] = mi;
    }
    for (int c = tid; c < 64; c += NTHREADS) {
        int gr = (c & 3)*HID + gb*16 + (c >> 2);
        bias[c] = b_ih[gr] + b_hh[gr];
        for (int d = 0; d < DDIM; ++d) wih[c*12 + d] = W_ih[gr*DDIM + d];
    }
    // initial h in all layouts (CTA covers 1/128 of 512x512)
    for (int idx = bx*2048 + tid; idx < (bx+1)*2048; idx += NTHREADS) {
        int r = idx >> 9, j = idx & 511;
        float v = h0[j];
        g_hrm[0][(size_t)r*HID + j] = v;
        int mbb = r >> 7, m = r & 127;
        int ci = (j>>4)*256 + (m>>4)*32 + (m&7)*4 + ((j&7)>>1);
        int pos = 2*((m>>3)&1) + 4*((j>>3)&1) + (j&1);
        ushort_t hi = bf16u(v);
        g_habf[0][mbb*65536 + ci*8 + pos] = hi;
        g_hmbf[0][mbb*65536 + ci*8 + pos] = bf16u(v - bf16f(hi));
    }
    // c state: all 512 threads, 4 units each (row = tid>>2, units (tid&3)*4..+3)
    float c_reg[4];
    {
        const int u0 = (tid & 3)*4;
#pragma unroll
        for (int q = 0; q < 4; ++q) c_reg[q] = c0[gb*16 + u0 + q];
    }
    bar_sync(4, NCTA);

    // per-warp fragment offsets (uint4 index within a kb16 slab of 256)
    const int aoff = wm*32 + lane;                  // one m16 tile per warp
    const int boff = wn*4*32 + lane;                // 4 n8 tiles per warp

    // ---- time loop ----
    for (int s = 0; s < NSTEPS; ++s) {
        const int rb = s & 1;
        const uint4* __restrict__ hsrc = (const uint4*)(g_habf[rb] + mb*65536);
        const uint4* __restrict__ msrc = (const uint4*)(g_hmbf[rb] + mb*65536);
        const float* __restrict__ hrm_in = g_hrm[rb];
        const bool enc = (s < TENC);

        float d[4][4];
#pragma unroll
        for (int nt = 0; nt < 4; ++nt)
#pragma unroll
            for (int q = 0; q < 4; ++q) d[nt][q] = 0.0f;

        // A pipeline prologue (LDG latency covered by fc/xp below)
        uint4 Ah[DEPTH], Am[DEPTH];
#pragma unroll
        for (int p = 0; p < DEPTH; ++p) {
            Ah[p] = __ldcg(hsrc + p*256 + aoff);
            Am[p] = __ldcg(msrc + p*256 + aoff);
        }

        if (s >= TENC + 1)
            fc_out(hrm_in, fcW, fcb, out, m0 + gb*4, s - (TENC+1), wid, lane);

        if (enc) {   // x-projection + bias -> xp[row][64]
            const int xrow = tid >> 2, cb = (tid & 3)*16;
            float xv[DDIM];
#pragma unroll
            for (int dd = 0; dd < DDIM; ++dd)
                xv[dd] = __ldg(x + (size_t)(m0 + xrow)*(TENC*DDIM) + s*DDIM + dd);
            float sg[16];
#pragma unroll
            for (int c = 0; c < 16; ++c) sg[c] = bias[cb + c];
#pragma unroll
            for (int dd = 0; dd < DDIM; ++dd)
#pragma unroll
                for (int c = 0; c < 16; ++c) sg[c] += xv[dd]*wih[(cb + c)*12 + dd];
#pragma unroll
            for (int c = 0; c < 16; c += 4)
                *(float4*)(xp + xrow*XPS + cb + c) =
                    make_float4(sg[c], sg[c+1], sg[c+2], sg[c+3]);
        }

        // ---- GEMM: 32 k16-blocks, sync-free; B from persistent smem ----
#pragma unroll
        for (int kb = 0; kb < 32; ++kb) {
            const int slot = kb & (DEPTH - 1);
            const uint4 A1 = Ah[slot], A2 = Am[slot];
            if (kb + DEPTH < 32) {
                Ah[slot] = __ldcg(hsrc + (kb+DEPTH)*256 + aoff);
                Am[slot] = __ldcg(msrc + (kb+DEPTH)*256 + aoff);
            }
#pragma unroll
            for (int nt = 0; nt < 4; ++nt) {
                const uint4 B = wsm4[kb*256 + boff + nt*32];
                mma16(d[nt], A1, B.x, B.y);   // hi*hi
                mma16(d[nt], A1, B.z, B.w);   // hi*mid
                mma16(d[nt], A2, B.x, B.y);   // mid*hi
            }
        }

        // ---- epilogue ----
        {
            const int g = lane >> 2, tq = lane & 3;
#pragma unroll
            for (int nt = 0; nt < 4; ++nt) {
                const int row = wm*16 + g;
                const int col = wn*32 + nt*8 + tq*2;
                *(float2*)(ds + row*XPS + col)     = make_float2(d[nt][0], d[nt][1]);
                *(float2*)(ds + (row+8)*XPS + col) = make_float2(d[nt][2], d[nt][3]);
            }
        }
        __syncthreads();
        {
            const int row = tid >> 2;          // 0..127
            const int u0 = (tid & 3)*4;        // 4 units per thread
            float hv[4];
#pragma unroll
            for (int q = 0; q < 4; ++q) {
                const int u = u0 + q;
                float4 gv = *(float4*)(ds + row*XPS + u*4);
                float ai, af, ag, ao;
                if (enc) {
                    float4 a = *(float4*)(xp + row*XPS + u*4);
                    ai = a.x; af = a.y; ag = a.z; ao = a.w;
                } else {
                    ai = bias[u*4]; af = bias[u*4+1]; ag = bias[u*4+2]; ao = bias[u*4+3];
                }
                float iv = gv.x + ai, fv = gv.y + af, gg = gv.z + ag, ov = gv.w + ao;
                float cn = sigf(fv)*c_reg[q] + sigf(iv)*tanhf(gg);
                c_reg[q] = cn;
                hv[q] = sigf(ov)*tanhf(cn);
            }
            // row-major fp32 for FC head (16B store)
            *(float4*)(g_hrm[rb ^ 1] + (size_t)(m0 + row)*HID + gb*16 + u0) =
                make_float4(hv[0], hv[1], hv[2], hv[3]);
            // bf16 split, fragment-order scatter into smem staging
#pragma unroll
            for (int q = 0; q < 4; ++q) {
                const int u = u0 + q;
                int ci = (row>>4)*32 + (row&7)*4 + ((u&7)>>1);
                int pos = 2*((row>>3)&1) + 4*((u>>3)&1) + (u&1);
                ushort_t hi = bf16u(hv[q]);
                hfh[ci*8 + pos] = hi;
                hfm[ci*8 + pos] = bf16u(hv[q] - bf16f(hi));
            }
        }
        __syncthreads();
        // linear copy staging -> global fragment-packed h
        if (tid < 256)
            ((uint4*)(g_habf[rb ^ 1] + mb*65536))[gb*256 + tid] = ((const uint4*)hfh)[tid];
        else
            ((uint4*)(g_hmbf[rb ^ 1] + mb*65536))[gb*256 + tid - 256] = ((const uint4*)hfm)[tid - 256];
        bar_sync(mb, 32);
    }

    fc_out(g_hrm[NSTEPS & 1], fcW, fcb, out, m0 + gb*4, TDEC - 1, wid, lane);
}

extern "C" void kernel_launch(void* const* d_in, const int* in_sizes, int n_in,
                              void* d_out, int out_size){
    (void)in_sizes; (void)n_in; (void)out_size;
    cudaFuncSetAttribute(lstm_kernel, cudaFuncAttributeMaxDynamicSharedMemorySize,
                         SMEM_BYTES);
    lstm_kernel<<<NCTA, NTHREADS, SMEM_BYTES>>>(
        (const float*)d_in[0], (const float*)d_in[1], (const float*)d_in[2],
        (const float*)d_in[3], (const float*)d_in[4], (const float*)d_in[5],
        (const float*)d_in[6], (const float*)d_in[7], (const float*)d_in[8],
        (float*)d_out);
}